// round 8
// baseline (speedup 1.0000x reference)
#include <cuda_runtime.h>
#include <math.h>
#include <stdint.h>

// Problem constants (fixed by the dataset)
#define NN      50000
#define EE_MAX  500000
#define ET_MAX  (NN + EE_MAX)
#define IND     384
#define HID1    1024   // 4 heads * 256
#define C1      256
#define H1      4
#define C2      128
#define NEG_SLOPE 0.2f

// converted-weight buffer offsets (floats)
#define OFF_ENC 0
#define CNT_ENC (384 * 384)
#define OFF_W1  (CNT_ENC)
#define CNT_W1  (384 * 1024)
#define OFF_W2  (OFF_W1 + CNT_W1)
#define CNT_W2  (1024 * 128)
#define CNT_WC  (OFF_W2 + CNT_W2)

// ---------------- scratch (static device globals; no allocation) -------------
static __device__ __align__(16) float g_h0  [(size_t)NN * IND];   // tf32-rounded
static __device__ __align__(16) float g_h1  [(size_t)NN * HID1];
static __device__ __align__(16) float g_o1  [(size_t)NN * HID1];  // tf32-rounded
static __device__ __align__(16) float g_h2  [(size_t)NN * C2];
static __device__ __align__(16) float g_xc  [(size_t)NN * IND];   // x -> tf32 bits
static __device__ __align__(16) float g_wc  [CNT_WC];             // weights -> tf32 bits

static __device__ __align__(16) float g_as1[NN * H1];
static __device__ __align__(16) float g_ad1[NN * H1];
static __device__ float g_as2[NN];
static __device__ float g_ad2[NN];

static __device__ __align__(16) float g_w1[(size_t)ET_MAX * H1];
static __device__ float g_w2[ET_MAX];

static __device__ int g_src[ET_MAX];
static __device__ int g_dst[ET_MAX];
static __device__ int g_deg[NN];
static __device__ int g_cursor[NN];
static __device__ int g_rowstart[NN + 1];
static __device__ int g_csr_src[ET_MAX];
static __device__ int g_is64;

// ---------------- mma helpers -------------------------------------------------
__device__ __forceinline__ uint32_t f2tf32(float f) {
    uint32_t u;
    asm("cvt.rna.tf32.f32 %0, %1;" : "=r"(u) : "f"(f));
    return u;
}
__device__ __forceinline__ float roundtf(float f) {
    return __uint_as_float(f2tf32(f));
}

__device__ __forceinline__ void mma_tf32(float* c, const uint32_t* a, const uint32_t* b) {
    asm volatile(
        "mma.sync.aligned.m16n8k8.row.col.f32.tf32.tf32.f32 "
        "{%0,%1,%2,%3},{%4,%5,%6,%7},{%8,%9},{%0,%1,%2,%3};"
        : "+f"(c[0]), "+f"(c[1]), "+f"(c[2]), "+f"(c[3])
        : "r"(a[0]), "r"(a[1]), "r"(a[2]), "r"(a[3]), "r"(b[0]), "r"(b[1]));
}

// ---------------- small kernels -----------------------------------------------

__global__ void k_detect(const void* ei) {
    const unsigned int* u = (const unsigned int*)ei;
    int is64 = 1;
    #pragma unroll
    for (int i = 1; i < 16; i += 2)
        if (u[i] != 0u) is64 = 0;
    g_is64 = is64;
}

// Build int32 src/dst with self-loops; fused destination histogram.
__global__ void k_prep(const void* ei, int E, int n) {
    int i = blockIdx.x * blockDim.x + threadIdx.x;
    int tot = E + n;
    if (i >= tot) return;
    int s, d;
    if (i < E) {
        if (g_is64) {
            const long long* p = (const long long*)ei;
            s = (int)p[i]; d = (int)p[E + i];
        } else {
            const int* p = (const int*)ei;
            s = p[i]; d = p[E + i];
        }
    } else {
        s = d = i - E;
    }
    g_src[i] = s; g_dst[i] = d;
    atomicAdd(&g_deg[d], 1);
}

__global__ void k_filli(int* p, int v, int count) {
    int i = blockIdx.x * blockDim.x + threadIdx.x;
    if (i < count) p[i] = v;
}

// fp32 -> tf32-bit fp32, float4 vectorized
__global__ void k_cvt4(const float* __restrict__ in, float* __restrict__ out, int n4) {
    int i = blockIdx.x * blockDim.x + threadIdx.x;
    if (i >= n4) return;
    float4 v = ((const float4*)in)[i];
    ((uint4*)out)[i] = make_uint4(f2tf32(v.x), f2tf32(v.y), f2tf32(v.z), f2tf32(v.w));
}

__global__ void __launch_bounds__(1024) k_scan(int n) {
    __shared__ int s_sum[1024];
    int t = threadIdx.x;
    const int CH = (NN + 1023) / 1024;   // 49
    int base = t * CH;
    int sum = 0;
    for (int i = 0; i < CH; i++) {
        int idx = base + i;
        if (idx < n) sum += g_deg[idx];
    }
    s_sum[t] = sum;
    __syncthreads();
    for (int o = 1; o < 1024; o <<= 1) {
        int v = 0;
        if (t >= o) v = s_sum[t - o];
        __syncthreads();
        if (t >= o) s_sum[t] += v;
        __syncthreads();
    }
    int run = (t > 0) ? s_sum[t - 1] : 0;
    for (int i = 0; i < CH; i++) {
        int idx = base + i;
        if (idx < n) { g_rowstart[idx] = run; run += g_deg[idx]; }
    }
    if (t == 1023) g_rowstart[n] = s_sum[1023];
}

__global__ void k_scatter(int tot) {
    int i = blockIdx.x * blockDim.x + threadIdx.x;
    if (i >= tot) return;
    int d = g_dst[i];
    int pos = atomicAdd(&g_cursor[d], 1);
    g_csr_src[g_rowstart[d] + pos] = g_src[i];
}

// ---------------- TF32 tensor-core GEMM ---------------------------------------
// C[M,N] = A[M,K] @ B[K,N], row-major; A,B already tf32-bit fp32.
// K%32==0, N%128==0. Block 128x128x32, 256 threads = 8 warps (4x2),
// warp tile 32x64. No register prefetch, no cvt -> low regs -> 2 CTAs/SM;
// latency hiding comes from cross-CTA overlap.
__global__ void __launch_bounds__(256, 2) k_gemm(
    const float* __restrict__ A, const float* __restrict__ B,
    float* __restrict__ C, int M, int N, int K)
{
    __shared__ uint32_t As[128][36];
    __shared__ uint32_t Bs[32][136];

    int tid = threadIdx.x;
    int lane = tid & 31;
    int wid = tid >> 5;
    int g = lane >> 2;        // 0..7
    int t = lane & 3;         // 0..3
    int warp_m = wid & 3;     // 0..3 (32 rows each)
    int warp_n = wid >> 2;    // 0..1 (64 cols each)
    int row0 = blockIdx.y * 128;
    int col0 = blockIdx.x * 128;

    float acc[2][8][4];
    #pragma unroll
    for (int mt = 0; mt < 2; mt++)
        #pragma unroll
        for (int nt = 0; nt < 8; nt++)
            #pragma unroll
            for (int i = 0; i < 4; i++) acc[mt][nt][i] = 0.f;

    int nIter = K >> 5;

    for (int it = 0; it < nIter; it++) {
        int k0g = it * 32;
        // load k-tile directly gmem -> smem (8 independent uint4 loads in flight)
        #pragma unroll
        for (int i = 0; i < 4; i++) {
            int idx = tid + 256 * i;
            int ar = idx >> 3, ac4 = idx & 7;
            int gr = row0 + ar;
            uint4 av = (gr < M) ? *(const uint4*)(A + (size_t)gr * K + k0g + ac4 * 4)
                                : make_uint4(0u, 0u, 0u, 0u);
            *(uint4*)&As[ar][ac4 * 4] = av;
            int br = idx >> 5, bc4 = idx & 31;
            uint4 bv = *(const uint4*)(B + (size_t)(k0g + br) * N + col0 + bc4 * 4);
            *(uint4*)&Bs[br][bc4 * 4] = bv;
        }
        __syncthreads();

        #pragma unroll
        for (int kk = 0; kk < 4; kk++) {
            int k0 = kk * 8;
            uint32_t af[2][4];
            #pragma unroll
            for (int mt = 0; mt < 2; mt++) {
                int mb = warp_m * 32 + mt * 16;
                af[mt][0] = As[mb + g][k0 + t];
                af[mt][1] = As[mb + g + 8][k0 + t];
                af[mt][2] = As[mb + g][k0 + t + 4];
                af[mt][3] = As[mb + g + 8][k0 + t + 4];
            }
            #pragma unroll
            for (int nt = 0; nt < 8; nt++) {
                uint32_t bf[2];
                int nb = warp_n * 64 + nt * 8;
                bf[0] = Bs[k0 + t][nb + g];
                bf[1] = Bs[k0 + t + 4][nb + g];
                mma_tf32(acc[0][nt], af[0], bf);
                mma_tf32(acc[1][nt], af[1], bf);
            }
        }
        __syncthreads();
    }

    // epilogue (plain store)
    #pragma unroll
    for (int mt = 0; mt < 2; mt++) {
        int r0 = row0 + warp_m * 32 + mt * 16 + g;
        #pragma unroll
        for (int nt = 0; nt < 8; nt++) {
            int c = col0 + warp_n * 64 + nt * 8 + 2 * t;
            if (r0 < M)
                *(float2*)(C + (size_t)r0 * N + c) = make_float2(acc[mt][nt][0], acc[mt][nt][1]);
            if (r0 + 8 < M)
                *(float2*)(C + (size_t)(r0 + 8) * N + c) = make_float2(acc[mt][nt][2], acc[mt][nt][3]);
        }
    }
}

// Encoder epilogue: h0 = roundtf(h0 + node_attr @ enc_W[384:386] + enc_b)
__global__ void k_enc_epi(const float* __restrict__ na,
                          const float* __restrict__ encW,
                          const float* __restrict__ encb, int n) {
    int idx = blockIdx.x * blockDim.x + threadIdx.x;     // float4 index
    int total = n * (IND / 4);
    if (idx >= total) return;
    int node = idx / (IND / 4);
    int j4 = idx - node * (IND / 4);
    float a0 = na[node * 2 + 0];
    float a1 = na[node * 2 + 1];
    float4 v  = *(float4*)(g_h0 + (size_t)idx * 4);
    float4 w0 = *(const float4*)(encW + (size_t)384 * IND + j4 * 4);
    float4 w1 = *(const float4*)(encW + (size_t)385 * IND + j4 * 4);
    float4 bb = *(const float4*)(encb + j4 * 4);
    v.x = roundtf(v.x + a0 * w0.x + a1 * w1.x + bb.x);
    v.y = roundtf(v.y + a0 * w0.y + a1 * w1.y + bb.y);
    v.z = roundtf(v.z + a0 * w0.z + a1 * w1.z + bb.z);
    v.w = roundtf(v.w + a0 * w0.w + a1 * w1.w + bb.w);
    *(float4*)(g_h0 + (size_t)idx * 4) = v;
}

// alpha_s / alpha_d for layer 1: one warp per (node, head)
__global__ void k_alpha1(const float* __restrict__ a_src,
                         const float* __restrict__ a_dst, int n) {
    int w = (blockIdx.x * blockDim.x + threadIdx.x) >> 5;
    int lane = threadIdx.x & 31;
    if (w >= n * H1) return;
    int node = w >> 2, head = w & 3;
    const float* hp = g_h1 + (size_t)node * HID1 + head * C1;
    const float* asp = a_src + head * C1;
    const float* adp = a_dst + head * C1;
    float s = 0.f, d = 0.f;
    #pragma unroll
    for (int c = lane; c < C1; c += 32) {
        float v = hp[c];
        s += v * asp[c];
        d += v * adp[c];
    }
    #pragma unroll
    for (int o = 16; o > 0; o >>= 1) {
        s += __shfl_xor_sync(0xffffffffu, s, o);
        d += __shfl_xor_sync(0xffffffffu, d, o);
    }
    if (lane == 0) { g_as1[node * H1 + head] = s; g_ad1[node * H1 + head] = d; }
}

// alpha_s / alpha_d for layer 2: one warp per node
__global__ void k_alpha2(const float* __restrict__ a_src,
                         const float* __restrict__ a_dst, int n) {
    int w = (blockIdx.x * blockDim.x + threadIdx.x) >> 5;
    int lane = threadIdx.x & 31;
    if (w >= n) return;
    const float* hp = g_h2 + (size_t)w * C2;
    float s = 0.f, d = 0.f;
    #pragma unroll
    for (int c = lane; c < C2; c += 32) {
        float v = hp[c];
        s += v * a_src[c];
        d += v * a_dst[c];
    }
    #pragma unroll
    for (int o = 16; o > 0; o >>= 1) {
        s += __shfl_xor_sync(0xffffffffu, s, o);
        d += __shfl_xor_sync(0xffffffffu, d, o);
    }
    if (lane == 0) { g_as2[w] = s; g_ad2[w] = d; }
}

__device__ __forceinline__ float leaky(float e) {
    return (e >= 0.f) ? e : NEG_SLOPE * e;
}

// Fused layer-1 attention softmax + aggregation + bias + ELU (tf32-rounded store).
// One 256-thread block per destination node.
__global__ void __launch_bounds__(256) k_attn_agg1(const float* __restrict__ b1) {
    int d = blockIdx.x;
    int t = threadIdx.x;
    int lane = t & 31;
    int beg = g_rowstart[d];
    int end = g_rowstart[d + 1];
    int deg = end - beg;

    __shared__ float s_inv[4];

    if (t < 32) {  // warp 0: softmax stats
        float4 ad = *(const float4*)(g_ad1 + d * 4);
        float m0 = -INFINITY, m1 = -INFINITY, m2 = -INFINITY, m3 = -INFINITY;
        for (int j = lane; j < deg; j += 32) {
            int s = g_csr_src[beg + j];
            float4 as = *(const float4*)(g_as1 + s * 4);
            float e0 = leaky(as.x + ad.x);
            float e1 = leaky(as.y + ad.y);
            float e2 = leaky(as.z + ad.z);
            float e3 = leaky(as.w + ad.w);
            *(float4*)(g_w1 + (size_t)(beg + j) * 4) = make_float4(e0, e1, e2, e3);
            m0 = fmaxf(m0, e0); m1 = fmaxf(m1, e1);
            m2 = fmaxf(m2, e2); m3 = fmaxf(m3, e3);
        }
        #pragma unroll
        for (int o = 16; o > 0; o >>= 1) {
            m0 = fmaxf(m0, __shfl_xor_sync(0xffffffffu, m0, o));
            m1 = fmaxf(m1, __shfl_xor_sync(0xffffffffu, m1, o));
            m2 = fmaxf(m2, __shfl_xor_sync(0xffffffffu, m2, o));
            m3 = fmaxf(m3, __shfl_xor_sync(0xffffffffu, m3, o));
        }
        float s0 = 0.f, s1 = 0.f, s2 = 0.f, s3 = 0.f;
        for (int j = lane; j < deg; j += 32) {
            float4 e = *(const float4*)(g_w1 + (size_t)(beg + j) * 4);
            float w0 = __expf(e.x - m0), w1 = __expf(e.y - m1);
            float w2 = __expf(e.z - m2), w3 = __expf(e.w - m3);
            *(float4*)(g_w1 + (size_t)(beg + j) * 4) = make_float4(w0, w1, w2, w3);
            s0 += w0; s1 += w1; s2 += w2; s3 += w3;
        }
        #pragma unroll
        for (int o = 16; o > 0; o >>= 1) {
            s0 += __shfl_xor_sync(0xffffffffu, s0, o);
            s1 += __shfl_xor_sync(0xffffffffu, s1, o);
            s2 += __shfl_xor_sync(0xffffffffu, s2, o);
            s3 += __shfl_xor_sync(0xffffffffu, s3, o);
        }
        if (lane == 0) {
            s_inv[0] = 1.f / (s0 + 1e-16f);
            s_inv[1] = 1.f / (s1 + 1e-16f);
            s_inv[2] = 1.f / (s2 + 1e-16f);
            s_inv[3] = 1.f / (s3 + 1e-16f);
        }
    }
    __syncthreads();

    float acc0 = 0.f, acc1 = 0.f, acc2 = 0.f, acc3 = 0.f;
    int j = 0;
    for (; j + 4 <= deg; j += 4) {
        int s0 = g_csr_src[beg + j];
        int s1 = g_csr_src[beg + j + 1];
        int s2 = g_csr_src[beg + j + 2];
        int s3 = g_csr_src[beg + j + 3];
        float4 w0 = *(const float4*)(g_w1 + (size_t)(beg + j) * 4);
        float4 w1 = *(const float4*)(g_w1 + (size_t)(beg + j + 1) * 4);
        float4 w2 = *(const float4*)(g_w1 + (size_t)(beg + j + 2) * 4);
        float4 w3 = *(const float4*)(g_w1 + (size_t)(beg + j + 3) * 4);
        const float* p0 = g_h1 + (size_t)s0 * HID1;
        const float* p1 = g_h1 + (size_t)s1 * HID1;
        const float* p2 = g_h1 + (size_t)s2 * HID1;
        const float* p3 = g_h1 + (size_t)s3 * HID1;
        acc0 += p0[t] * w0.x + p1[t] * w1.x + p2[t] * w2.x + p3[t] * w3.x;
        acc1 += p0[256 + t] * w0.y + p1[256 + t] * w1.y + p2[256 + t] * w2.y + p3[256 + t] * w3.y;
        acc2 += p0[512 + t] * w0.z + p1[512 + t] * w1.z + p2[512 + t] * w2.z + p3[512 + t] * w3.z;
        acc3 += p0[768 + t] * w0.w + p1[768 + t] * w1.w + p2[768 + t] * w2.w + p3[768 + t] * w3.w;
    }
    for (; j < deg; j++) {
        int s = g_csr_src[beg + j];
        float4 w = *(const float4*)(g_w1 + (size_t)(beg + j) * 4);
        const float* hs = g_h1 + (size_t)s * HID1;
        acc0 += hs[t] * w.x;
        acc1 += hs[256 + t] * w.y;
        acc2 += hs[512 + t] * w.z;
        acc3 += hs[768 + t] * w.w;
    }
    float v0 = acc0 * s_inv[0] + b1[t];
    float v1 = acc1 * s_inv[1] + b1[256 + t];
    float v2 = acc2 * s_inv[2] + b1[512 + t];
    float v3 = acc3 * s_inv[3] + b1[768 + t];
    float* od = g_o1 + (size_t)d * HID1;
    od[t]       = roundtf((v0 > 0.f) ? v0 : expm1f(v0));
    od[256 + t] = roundtf((v1 > 0.f) ? v1 : expm1f(v1));
    od[512 + t] = roundtf((v2 > 0.f) ? v2 : expm1f(v2));
    od[768 + t] = roundtf((v3 > 0.f) ? v3 : expm1f(v3));
}

// Fused layer-2 attention softmax + aggregation + bias -> out.
// One 128-thread block per destination node.
__global__ void __launch_bounds__(128) k_attn_agg2(const float* __restrict__ b2,
                                                   float* __restrict__ out) {
    int d = blockIdx.x;
    int t = threadIdx.x;
    int lane = t & 31;
    int beg = g_rowstart[d];
    int end = g_rowstart[d + 1];
    int deg = end - beg;

    __shared__ float s_inv;

    if (t < 32) {
        float ad = g_ad2[d];
        float m = -INFINITY;
        for (int j = lane; j < deg; j += 32) {
            int s = g_csr_src[beg + j];
            float e = leaky(g_as2[s] + ad);
            g_w2[beg + j] = e;
            m = fmaxf(m, e);
        }
        #pragma unroll
        for (int o = 16; o > 0; o >>= 1)
            m = fmaxf(m, __shfl_xor_sync(0xffffffffu, m, o));
        float sum = 0.f;
        for (int j = lane; j < deg; j += 32) {
            float w = __expf(g_w2[beg + j] - m);
            g_w2[beg + j] = w;
            sum += w;
        }
        #pragma unroll
        for (int o = 16; o > 0; o >>= 1)
            sum += __shfl_xor_sync(0xffffffffu, sum, o);
        if (lane == 0) s_inv = 1.f / (sum + 1e-16f);
    }
    __syncthreads();

    float acc = 0.f;
    int j = 0;
    for (; j + 4 <= deg; j += 4) {
        int s0 = g_csr_src[beg + j];
        int s1 = g_csr_src[beg + j + 1];
        int s2 = g_csr_src[beg + j + 2];
        int s3 = g_csr_src[beg + j + 3];
        float w0 = g_w2[beg + j], w1 = g_w2[beg + j + 1];
        float w2 = g_w2[beg + j + 2], w3 = g_w2[beg + j + 3];
        acc += g_h2[(size_t)s0 * C2 + t] * w0 + g_h2[(size_t)s1 * C2 + t] * w1
             + g_h2[(size_t)s2 * C2 + t] * w2 + g_h2[(size_t)s3 * C2 + t] * w3;
    }
    for (; j < deg; j++) {
        int s = g_csr_src[beg + j];
        acc += g_h2[(size_t)s * C2 + t] * g_w2[beg + j];
    }
    out[(size_t)d * C2 + t] = acc * s_inv + b2[t];
}

// ---------------- host launcher ----------------------------------------------
extern "C" void kernel_launch(void* const* d_in, const int* in_sizes, int n_in,
                              void* d_out, int out_size) {
    const float* x       = (const float*)d_in[0];
    const float* na      = (const float*)d_in[1];
    const void*  ei      = d_in[2];
    const float* encW    = (const float*)d_in[3];
    const float* encb    = (const float*)d_in[4];
    const float* W1      = (const float*)d_in[5];
    const float* a_src1  = (const float*)d_in[6];
    const float* a_dst1  = (const float*)d_in[7];
    const float* b1      = (const float*)d_in[8];
    const float* W2      = (const float*)d_in[9];
    const float* a_src2  = (const float*)d_in[10];
    const float* a_dst2  = (const float*)d_in[11];
    const float* b2      = (const float*)d_in[12];
    float* out = (float*)d_out;

    int n = in_sizes[0] / IND;
    int E = in_sizes[2] / 2;
    int tot = E + n;

    int *p_deg, *p_cursor;
    cudaGetSymbolAddress((void**)&p_deg, g_deg);
    cudaGetSymbolAddress((void**)&p_cursor, g_cursor);
    float *p_h0, *p_h1, *p_o1, *p_h2, *p_xc, *p_wc;
    cudaGetSymbolAddress((void**)&p_h0, g_h0);
    cudaGetSymbolAddress((void**)&p_h1, g_h1);
    cudaGetSymbolAddress((void**)&p_o1, g_o1);
    cudaGetSymbolAddress((void**)&p_h2, g_h2);
    cudaGetSymbolAddress((void**)&p_xc, g_xc);
    cudaGetSymbolAddress((void**)&p_wc, g_wc);

    // ---- input conversion to tf32 bits ----
    k_cvt4<<<(n * (IND / 4) + 255) / 256, 256>>>(x, p_xc, n * (IND / 4));
    k_cvt4<<<(CNT_ENC / 4 + 255) / 256, 256>>>(encW, p_wc + OFF_ENC, CNT_ENC / 4);
    k_cvt4<<<(CNT_W1 / 4 + 255) / 256, 256>>>(W1, p_wc + OFF_W1, CNT_W1 / 4);
    k_cvt4<<<(CNT_W2 / 4 + 255) / 256, 256>>>(W2, p_wc + OFF_W2, CNT_W2 / 4);

    // ---- CSR build (hist fused into prep) ----
    k_detect<<<1, 1>>>(ei);
    k_filli<<<(n + 255) / 256, 256>>>(p_deg, 0, n);
    k_filli<<<(n + 255) / 256, 256>>>(p_cursor, 0, n);
    k_prep<<<(tot + 255) / 256, 256>>>(ei, E, n);

    // ---- encoder GEMM + epilogue ----
    {
        dim3 grid(IND / 128, (n + 127) / 128);
        k_gemm<<<grid, 256>>>(p_xc, p_wc + OFF_ENC, p_h0, n, IND, IND);
        k_enc_epi<<<(n * (IND / 4) + 255) / 256, 256>>>(na, encW, encb, n);
    }

    // CSR back half
    k_scan<<<1, 1024>>>(n);
    k_scatter<<<(tot + 255) / 256, 256>>>(tot);

    // ---- GAT layer 1 ----
    {
        dim3 grid(HID1 / 128, (n + 127) / 128);
        k_gemm<<<grid, 256>>>(p_h0, p_wc + OFF_W1, p_h1, n, HID1, IND);
    }
    k_alpha1<<<((n * H1 * 32) + 127) / 128, 128>>>(a_src1, a_dst1, n);
    k_attn_agg1<<<n, 256>>>(b1);

    // ---- GAT layer 2 ----
    {
        dim3 grid(C2 / 128, (n + 127) / 128);
        k_gemm<<<grid, 256>>>(p_o1, p_wc + OFF_W2, p_h2, n, C2, HID1);
    }
    k_alpha2<<<((n * 32) + 127) / 128, 128>>>(a_src2, a_dst2, n);
    k_attn_agg2<<<n, 128>>>(b2, out);
}

// round 9
// speedup vs baseline: 1.0563x; 1.0563x over previous
#include <cuda_runtime.h>
#include <math.h>
#include <stdint.h>

// Problem constants (fixed by the dataset)
#define NN      50000
#define EE_MAX  500000
#define ET_MAX  (NN + EE_MAX)
#define IND     384
#define HID1    1024   // 4 heads * 256
#define C1      256
#define H1      4
#define C2      128
#define NEG_SLOPE 0.2f

// ---------------- scratch (static device globals; no allocation) -------------
static __device__ __align__(16) float g_h0  [(size_t)NN * IND];
static __device__ __align__(16) float g_h1  [(size_t)NN * HID1];
static __device__ __align__(16) float g_o1  [(size_t)NN * HID1];  // layer-1 output (post ELU)
static __device__ __align__(16) float g_h2  [(size_t)NN * C2];

static __device__ __align__(16) float g_as1[NN * H1];
static __device__ __align__(16) float g_ad1[NN * H1];
static __device__ float g_as2[NN];
static __device__ float g_ad2[NN];

static __device__ __align__(16) float g_w1[(size_t)ET_MAX * H1];
static __device__ float g_w2[ET_MAX];

static __device__ int g_src[ET_MAX];
static __device__ int g_dst[ET_MAX];
static __device__ int g_deg[NN];
static __device__ int g_cursor[NN];
static __device__ int g_rowstart[NN + 1];
static __device__ int g_csr_src[ET_MAX];
static __device__ int g_is64;

// ---------------- mma helpers -------------------------------------------------
__device__ __forceinline__ uint32_t f2tf32(float f) {
    uint32_t u;
    asm("cvt.rna.tf32.f32 %0, %1;" : "=r"(u) : "f"(f));
    return u;
}

__device__ __forceinline__ void mma_tf32(float* c, const uint32_t* a, const uint32_t* b) {
    asm volatile(
        "mma.sync.aligned.m16n8k8.row.col.f32.tf32.tf32.f32 "
        "{%0,%1,%2,%3},{%4,%5,%6,%7},{%8,%9},{%0,%1,%2,%3};"
        : "+f"(c[0]), "+f"(c[1]), "+f"(c[2]), "+f"(c[3])
        : "r"(a[0]), "r"(a[1]), "r"(a[2]), "r"(a[3]), "r"(b[0]), "r"(b[1]));
}

// ---------------- small kernels -----------------------------------------------

__global__ void k_detect(const void* ei) {
    const unsigned int* u = (const unsigned int*)ei;
    int is64 = 1;
    #pragma unroll
    for (int i = 1; i < 16; i += 2)
        if (u[i] != 0u) is64 = 0;
    g_is64 = is64;
}

// zero deg + cursor in one pass
__global__ void k_init(int n) {
    int i = blockIdx.x * blockDim.x + threadIdx.x;
    if (i < n) { g_deg[i] = 0; g_cursor[i] = 0; }
}

// Build int32 src/dst lists with self-loops appended; fused degree histogram.
__global__ void k_prep(const void* ei, int E, int n) {
    int i = blockIdx.x * blockDim.x + threadIdx.x;
    int tot = E + n;
    if (i >= tot) return;
    int s, d;
    if (i < E) {
        if (g_is64) {
            const long long* p = (const long long*)ei;
            s = (int)p[i]; d = (int)p[E + i];
        } else {
            const int* p = (const int*)ei;
            s = p[i]; d = p[E + i];
        }
    } else {
        s = d = i - E;
    }
    g_src[i] = s; g_dst[i] = d;
    atomicAdd(&g_deg[d], 1);
}

__global__ void __launch_bounds__(1024) k_scan(int n) {
    __shared__ int s_sum[1024];
    int t = threadIdx.x;
    const int CH = (NN + 1023) / 1024;   // 49
    int base = t * CH;
    int sum = 0;
    for (int i = 0; i < CH; i++) {
        int idx = base + i;
        if (idx < n) sum += g_deg[idx];
    }
    s_sum[t] = sum;
    __syncthreads();
    for (int o = 1; o < 1024; o <<= 1) {
        int v = 0;
        if (t >= o) v = s_sum[t - o];
        __syncthreads();
        if (t >= o) s_sum[t] += v;
        __syncthreads();
    }
    int run = (t > 0) ? s_sum[t - 1] : 0;
    for (int i = 0; i < CH; i++) {
        int idx = base + i;
        if (idx < n) { g_rowstart[idx] = run; run += g_deg[idx]; }
    }
    if (t == 1023) g_rowstart[n] = s_sum[1023];
}

__global__ void k_scatter(int tot) {
    int i = blockIdx.x * blockDim.x + threadIdx.x;
    if (i >= tot) return;
    int d = g_dst[i];
    int pos = atomicAdd(&g_cursor[d], 1);
    g_csr_src[g_rowstart[d] + pos] = g_src[i];
}

// ---------------- TF32 tensor-core GEMM (round-3 proven config) ---------------
// C[M,N] = A[M,K] @ B[K,N], row-major. Requires K%32==0, N%128==0.
// Block: 128x128x32, 256 threads = 8 warps (4x2), warp tile 32x64,
// mma.m16n8k8 tf32, register-prefetch single-buffer pipeline.
__global__ void __launch_bounds__(256, 1) k_mma_gemm(
    const float* __restrict__ A, const float* __restrict__ B,
    float* __restrict__ C, int M, int N, int K)
{
    __shared__ uint32_t As[128][36];
    __shared__ uint32_t Bs[32][136];

    int tid = threadIdx.x;
    int lane = tid & 31;
    int wid = tid >> 5;
    int g = lane >> 2;        // 0..7
    int t = lane & 3;         // 0..3
    int warp_m = wid & 3;     // 0..3 (32 rows each)
    int warp_n = wid >> 2;    // 0..1 (64 cols each)
    int row0 = blockIdx.y * 128;
    int col0 = blockIdx.x * 128;

    float acc[2][8][4];
    #pragma unroll
    for (int mt = 0; mt < 2; mt++)
        #pragma unroll
        for (int nt = 0; nt < 8; nt++)
            #pragma unroll
            for (int i = 0; i < 4; i++) acc[mt][nt][i] = 0.f;

    float4 pa[4], pb[4];
    int nIter = K >> 5;

    // prologue: load k-tile 0
    #pragma unroll
    for (int i = 0; i < 4; i++) {
        int idx = tid + 256 * i;
        int ar = idx >> 3, ac4 = idx & 7;
        int gr = row0 + ar;
        pa[i] = (gr < M) ? *(const float4*)(A + (size_t)gr * K + ac4 * 4)
                         : make_float4(0.f, 0.f, 0.f, 0.f);
        int br = idx >> 5, bc4 = idx & 31;
        pb[i] = *(const float4*)(B + (size_t)br * N + col0 + bc4 * 4);
    }
    #pragma unroll
    for (int i = 0; i < 4; i++) {
        int idx = tid + 256 * i;
        int ar = idx >> 3, ac4 = idx & 7;
        uint4 av = make_uint4(f2tf32(pa[i].x), f2tf32(pa[i].y), f2tf32(pa[i].z), f2tf32(pa[i].w));
        *(uint4*)&As[ar][ac4 * 4] = av;
        int br = idx >> 5, bc4 = idx & 31;
        uint4 bv = make_uint4(f2tf32(pb[i].x), f2tf32(pb[i].y), f2tf32(pb[i].z), f2tf32(pb[i].w));
        *(uint4*)&Bs[br][bc4 * 4] = bv;
    }
    __syncthreads();

    for (int it = 0; it < nIter; it++) {
        bool more = (it + 1 < nIter);
        if (more) {
            int k0g = (it + 1) * 32;
            #pragma unroll
            for (int i = 0; i < 4; i++) {
                int idx = tid + 256 * i;
                int ar = idx >> 3, ac4 = idx & 7;
                int gr = row0 + ar;
                pa[i] = (gr < M) ? *(const float4*)(A + (size_t)gr * K + k0g + ac4 * 4)
                                 : make_float4(0.f, 0.f, 0.f, 0.f);
                int br = idx >> 5, bc4 = idx & 31;
                pb[i] = *(const float4*)(B + (size_t)(k0g + br) * N + col0 + bc4 * 4);
            }
        }

        // compute on current smem tile
        #pragma unroll
        for (int kk = 0; kk < 4; kk++) {
            int k0 = kk * 8;
            uint32_t af[2][4];
            #pragma unroll
            for (int mt = 0; mt < 2; mt++) {
                int mb = warp_m * 32 + mt * 16;
                af[mt][0] = As[mb + g][k0 + t];
                af[mt][1] = As[mb + g + 8][k0 + t];
                af[mt][2] = As[mb + g][k0 + t + 4];
                af[mt][3] = As[mb + g + 8][k0 + t + 4];
            }
            #pragma unroll
            for (int nt = 0; nt < 8; nt++) {
                uint32_t bf[2];
                int nb = warp_n * 64 + nt * 8;
                bf[0] = Bs[k0 + t][nb + g];
                bf[1] = Bs[k0 + t + 4][nb + g];
                mma_tf32(acc[0][nt], af[0], bf);
                mma_tf32(acc[1][nt], af[1], bf);
            }
        }

        if (more) {
            __syncthreads();
            #pragma unroll
            for (int i = 0; i < 4; i++) {
                int idx = tid + 256 * i;
                int ar = idx >> 3, ac4 = idx & 7;
                uint4 av = make_uint4(f2tf32(pa[i].x), f2tf32(pa[i].y), f2tf32(pa[i].z), f2tf32(pa[i].w));
                *(uint4*)&As[ar][ac4 * 4] = av;
                int br = idx >> 5, bc4 = idx & 31;
                uint4 bv = make_uint4(f2tf32(pb[i].x), f2tf32(pb[i].y), f2tf32(pb[i].z), f2tf32(pb[i].w));
                *(uint4*)&Bs[br][bc4 * 4] = bv;
            }
            __syncthreads();
        }
    }

    // epilogue
    #pragma unroll
    for (int mt = 0; mt < 2; mt++) {
        int r0 = row0 + warp_m * 32 + mt * 16 + g;
        #pragma unroll
        for (int nt = 0; nt < 8; nt++) {
            int c = col0 + warp_n * 64 + nt * 8 + 2 * t;
            if (r0 < M)
                *(float2*)(C + (size_t)r0 * N + c) = make_float2(acc[mt][nt][0], acc[mt][nt][1]);
            if (r0 + 8 < M)
                *(float2*)(C + (size_t)(r0 + 8) * N + c) = make_float2(acc[mt][nt][2], acc[mt][nt][3]);
        }
    }
}

// Encoder epilogue: h0 += node_attr @ enc_W[384:386] + enc_b   (float4)
__global__ void k_enc_epi(const float* __restrict__ na,
                          const float* __restrict__ encW,
                          const float* __restrict__ encb, int n) {
    int idx = blockIdx.x * blockDim.x + threadIdx.x;     // float4 index
    int total = n * (IND / 4);
    if (idx >= total) return;
    int node = idx / (IND / 4);
    int j4 = idx - node * (IND / 4);
    float a0 = na[node * 2 + 0];
    float a1 = na[node * 2 + 1];
    float4 v  = *(float4*)(g_h0 + (size_t)idx * 4);
    float4 w0 = *(const float4*)(encW + (size_t)384 * IND + j4 * 4);
    float4 w1 = *(const float4*)(encW + (size_t)385 * IND + j4 * 4);
    float4 bb = *(const float4*)(encb + j4 * 4);
    v.x += a0 * w0.x + a1 * w1.x + bb.x;
    v.y += a0 * w0.y + a1 * w1.y + bb.y;
    v.z += a0 * w0.z + a1 * w1.z + bb.z;
    v.w += a0 * w0.w + a1 * w1.w + bb.w;
    *(float4*)(g_h0 + (size_t)idx * 4) = v;
}

// alpha_s / alpha_d for layer 1: one warp per (node, head)
__global__ void k_alpha1(const float* __restrict__ a_src,
                         const float* __restrict__ a_dst, int n) {
    int w = (blockIdx.x * blockDim.x + threadIdx.x) >> 5;
    int lane = threadIdx.x & 31;
    if (w >= n * H1) return;
    int node = w >> 2, head = w & 3;
    const float* hp = g_h1 + (size_t)node * HID1 + head * C1;
    const float* asp = a_src + head * C1;
    const float* adp = a_dst + head * C1;
    float s = 0.f, d = 0.f;
    #pragma unroll
    for (int c = lane; c < C1; c += 32) {
        float v = hp[c];
        s += v * asp[c];
        d += v * adp[c];
    }
    #pragma unroll
    for (int o = 16; o > 0; o >>= 1) {
        s += __shfl_xor_sync(0xffffffffu, s, o);
        d += __shfl_xor_sync(0xffffffffu, d, o);
    }
    if (lane == 0) { g_as1[node * H1 + head] = s; g_ad1[node * H1 + head] = d; }
}

// alpha_s / alpha_d for layer 2: one warp per node
__global__ void k_alpha2(const float* __restrict__ a_src,
                         const float* __restrict__ a_dst, int n) {
    int w = (blockIdx.x * blockDim.x + threadIdx.x) >> 5;
    int lane = threadIdx.x & 31;
    if (w >= n) return;
    const float* hp = g_h2 + (size_t)w * C2;
    float s = 0.f, d = 0.f;
    #pragma unroll
    for (int c = lane; c < C2; c += 32) {
        float v = hp[c];
        s += v * a_src[c];
        d += v * a_dst[c];
    }
    #pragma unroll
    for (int o = 16; o > 0; o >>= 1) {
        s += __shfl_xor_sync(0xffffffffu, s, o);
        d += __shfl_xor_sync(0xffffffffu, d, o);
    }
    if (lane == 0) { g_as2[w] = s; g_ad2[w] = d; }
}

__device__ __forceinline__ float leaky(float e) {
    return (e >= 0.f) ? e : NEG_SLOPE * e;
}

// Fused layer-1 attention softmax + aggregation + bias + ELU.
// One 256-thread block per destination node.
__global__ void __launch_bounds__(256) k_attn_agg1(const float* __restrict__ b1) {
    int d = blockIdx.x;
    int t = threadIdx.x;
    int lane = t & 31;
    int beg = g_rowstart[d];
    int end = g_rowstart[d + 1];
    int deg = end - beg;

    __shared__ float s_inv[4];

    if (t < 32) {  // warp 0: softmax stats
        float4 ad = *(const float4*)(g_ad1 + d * 4);
        float m0 = -INFINITY, m1 = -INFINITY, m2 = -INFINITY, m3 = -INFINITY;
        for (int j = lane; j < deg; j += 32) {
            int s = g_csr_src[beg + j];
            float4 as = *(const float4*)(g_as1 + s * 4);
            float e0 = leaky(as.x + ad.x);
            float e1 = leaky(as.y + ad.y);
            float e2 = leaky(as.z + ad.z);
            float e3 = leaky(as.w + ad.w);
            *(float4*)(g_w1 + (size_t)(beg + j) * 4) = make_float4(e0, e1, e2, e3);
            m0 = fmaxf(m0, e0); m1 = fmaxf(m1, e1);
            m2 = fmaxf(m2, e2); m3 = fmaxf(m3, e3);
        }
        #pragma unroll
        for (int o = 16; o > 0; o >>= 1) {
            m0 = fmaxf(m0, __shfl_xor_sync(0xffffffffu, m0, o));
            m1 = fmaxf(m1, __shfl_xor_sync(0xffffffffu, m1, o));
            m2 = fmaxf(m2, __shfl_xor_sync(0xffffffffu, m2, o));
            m3 = fmaxf(m3, __shfl_xor_sync(0xffffffffu, m3, o));
        }
        float s0 = 0.f, s1 = 0.f, s2 = 0.f, s3 = 0.f;
        for (int j = lane; j < deg; j += 32) {
            float4 e = *(const float4*)(g_w1 + (size_t)(beg + j) * 4);
            float w0 = __expf(e.x - m0), w1 = __expf(e.y - m1);
            float w2 = __expf(e.z - m2), w3 = __expf(e.w - m3);
            *(float4*)(g_w1 + (size_t)(beg + j) * 4) = make_float4(w0, w1, w2, w3);
            s0 += w0; s1 += w1; s2 += w2; s3 += w3;
        }
        #pragma unroll
        for (int o = 16; o > 0; o >>= 1) {
            s0 += __shfl_xor_sync(0xffffffffu, s0, o);
            s1 += __shfl_xor_sync(0xffffffffu, s1, o);
            s2 += __shfl_xor_sync(0xffffffffu, s2, o);
            s3 += __shfl_xor_sync(0xffffffffu, s3, o);
        }
        if (lane == 0) {
            s_inv[0] = 1.f / (s0 + 1e-16f);
            s_inv[1] = 1.f / (s1 + 1e-16f);
            s_inv[2] = 1.f / (s2 + 1e-16f);
            s_inv[3] = 1.f / (s3 + 1e-16f);
        }
    }
    __syncthreads();

    float acc0 = 0.f, acc1 = 0.f, acc2 = 0.f, acc3 = 0.f;
    int j = 0;
    for (; j + 4 <= deg; j += 4) {
        int s0 = g_csr_src[beg + j];
        int s1 = g_csr_src[beg + j + 1];
        int s2 = g_csr_src[beg + j + 2];
        int s3 = g_csr_src[beg + j + 3];
        float4 w0 = *(const float4*)(g_w1 + (size_t)(beg + j) * 4);
        float4 w1 = *(const float4*)(g_w1 + (size_t)(beg + j + 1) * 4);
        float4 w2 = *(const float4*)(g_w1 + (size_t)(beg + j + 2) * 4);
        float4 w3 = *(const float4*)(g_w1 + (size_t)(beg + j + 3) * 4);
        const float* p0 = g_h1 + (size_t)s0 * HID1;
        const float* p1 = g_h1 + (size_t)s1 * HID1;
        const float* p2 = g_h1 + (size_t)s2 * HID1;
        const float* p3 = g_h1 + (size_t)s3 * HID1;
        acc0 += p0[t] * w0.x + p1[t] * w1.x + p2[t] * w2.x + p3[t] * w3.x;
        acc1 += p0[256 + t] * w0.y + p1[256 + t] * w1.y + p2[256 + t] * w2.y + p3[256 + t] * w3.y;
        acc2 += p0[512 + t] * w0.z + p1[512 + t] * w1.z + p2[512 + t] * w2.z + p3[512 + t] * w3.z;
        acc3 += p0[768 + t] * w0.w + p1[768 + t] * w1.w + p2[768 + t] * w2.w + p3[768 + t] * w3.w;
    }
    for (; j < deg; j++) {
        int s = g_csr_src[beg + j];
        float4 w = *(const float4*)(g_w1 + (size_t)(beg + j) * 4);
        const float* hs = g_h1 + (size_t)s * HID1;
        acc0 += hs[t] * w.x;
        acc1 += hs[256 + t] * w.y;
        acc2 += hs[512 + t] * w.z;
        acc3 += hs[768 + t] * w.w;
    }
    float v0 = acc0 * s_inv[0] + b1[t];
    float v1 = acc1 * s_inv[1] + b1[256 + t];
    float v2 = acc2 * s_inv[2] + b1[512 + t];
    float v3 = acc3 * s_inv[3] + b1[768 + t];
    float* od = g_o1 + (size_t)d * HID1;
    od[t]       = (v0 > 0.f) ? v0 : expm1f(v0);
    od[256 + t] = (v1 > 0.f) ? v1 : expm1f(v1);
    od[512 + t] = (v2 > 0.f) ? v2 : expm1f(v2);
    od[768 + t] = (v3 > 0.f) ? v3 : expm1f(v3);
}

// Fused layer-2 attention softmax + aggregation + bias -> out.
// One 128-thread block per destination node.
__global__ void __launch_bounds__(128) k_attn_agg2(const float* __restrict__ b2,
                                                   float* __restrict__ out) {
    int d = blockIdx.x;
    int t = threadIdx.x;
    int lane = t & 31;
    int beg = g_rowstart[d];
    int end = g_rowstart[d + 1];
    int deg = end - beg;

    __shared__ float s_inv;

    if (t < 32) {
        float ad = g_ad2[d];
        float m = -INFINITY;
        for (int j = lane; j < deg; j += 32) {
            int s = g_csr_src[beg + j];
            float e = leaky(g_as2[s] + ad);
            g_w2[beg + j] = e;
            m = fmaxf(m, e);
        }
        #pragma unroll
        for (int o = 16; o > 0; o >>= 1)
            m = fmaxf(m, __shfl_xor_sync(0xffffffffu, m, o));
        float sum = 0.f;
        for (int j = lane; j < deg; j += 32) {
            float w = __expf(g_w2[beg + j] - m);
            g_w2[beg + j] = w;
            sum += w;
        }
        #pragma unroll
        for (int o = 16; o > 0; o >>= 1)
            sum += __shfl_xor_sync(0xffffffffu, sum, o);
        if (lane == 0) s_inv = 1.f / (sum + 1e-16f);
    }
    __syncthreads();

    float acc = 0.f;
    int j = 0;
    for (; j + 4 <= deg; j += 4) {
        int s0 = g_csr_src[beg + j];
        int s1 = g_csr_src[beg + j + 1];
        int s2 = g_csr_src[beg + j + 2];
        int s3 = g_csr_src[beg + j + 3];
        float w0 = g_w2[beg + j], w1 = g_w2[beg + j + 1];
        float w2 = g_w2[beg + j + 2], w3 = g_w2[beg + j + 3];
        acc += g_h2[(size_t)s0 * C2 + t] * w0 + g_h2[(size_t)s1 * C2 + t] * w1
             + g_h2[(size_t)s2 * C2 + t] * w2 + g_h2[(size_t)s3 * C2 + t] * w3;
    }
    for (; j < deg; j++) {
        int s = g_csr_src[beg + j];
        acc += g_h2[(size_t)s * C2 + t] * g_w2[beg + j];
    }
    out[(size_t)d * C2 + t] = acc * s_inv + b2[t];
}

// ---------------- host launcher ----------------------------------------------
extern "C" void kernel_launch(void* const* d_in, const int* in_sizes, int n_in,
                              void* d_out, int out_size) {
    const float* x       = (const float*)d_in[0];
    const float* na      = (const float*)d_in[1];
    const void*  ei      = d_in[2];
    const float* encW    = (const float*)d_in[3];
    const float* encb    = (const float*)d_in[4];
    const float* W1      = (const float*)d_in[5];
    const float* a_src1  = (const float*)d_in[6];
    const float* a_dst1  = (const float*)d_in[7];
    const float* b1      = (const float*)d_in[8];
    const float* W2      = (const float*)d_in[9];
    const float* a_src2  = (const float*)d_in[10];
    const float* a_dst2  = (const float*)d_in[11];
    const float* b2      = (const float*)d_in[12];
    float* out = (float*)d_out;

    int n = in_sizes[0] / IND;
    int E = in_sizes[2] / 2;
    int tot = E + n;

    float *p_h0, *p_h1, *p_o1, *p_h2;
    cudaGetSymbolAddress((void**)&p_h0, g_h0);
    cudaGetSymbolAddress((void**)&p_h1, g_h1);
    cudaGetSymbolAddress((void**)&p_o1, g_o1);
    cudaGetSymbolAddress((void**)&p_h2, g_h2);

    // ---- CSR build ----
    k_detect<<<1, 1>>>(ei);
    k_init<<<(n + 255) / 256, 256>>>(n);
    k_prep<<<(tot + 255) / 256, 256>>>(ei, E, n);

    // ---- encoder ----
    {
        dim3 grid(IND / 128, (n + 127) / 128);
        k_mma_gemm<<<grid, 256>>>(x, encW, p_h0, n, IND, IND);
        k_enc_epi<<<(n * (IND / 4) + 255) / 256, 256>>>(na, encW, encb, n);
    }

    // CSR back half (overlap-friendly ordering)
    k_scan<<<1, 1024>>>(n);
    k_scatter<<<(tot + 255) / 256, 256>>>(tot);

    // ---- GAT layer 1 ----
    {
        dim3 grid(HID1 / 128, (n + 127) / 128);
        k_mma_gemm<<<grid, 256>>>(p_h0, W1, p_h1, n, HID1, IND);
    }
    k_alpha1<<<((n * H1 * 32) + 127) / 128, 128>>>(a_src1, a_dst1, n);
    k_attn_agg1<<<n, 256>>>(b1);

    // ---- GAT layer 2 ----
    {
        dim3 grid(C2 / 128, (n + 127) / 128);
        k_mma_gemm<<<grid, 256>>>(p_o1, W2, p_h2, n, C2, HID1);
    }
    k_alpha2<<<((n * 32) + 127) / 128, 128>>>(a_src2, a_dst2, n);
    k_attn_agg2<<<n, 128>>>(b2, out);
}

// round 10
// speedup vs baseline: 1.0833x; 1.0256x over previous
#include <cuda_runtime.h>
#include <math.h>
#include <stdint.h>

// Problem constants (fixed by the dataset)
#define NN      50000
#define EE_MAX  500000
#define ET_MAX  (NN + EE_MAX)
#define IND     384
#define HID1    1024   // 4 heads * 256
#define C1      256
#define H1      4
#define C2      128
#define NEG_SLOPE 0.2f

// transposed-weight buffer offsets (floats)
#define OFF_ENC 0
#define CNT_ENC (384 * 384)
#define OFF_W1  (CNT_ENC)
#define CNT_W1  (384 * 1024)
#define OFF_W2  (OFF_W1 + CNT_W1)
#define CNT_W2  (1024 * 128)
#define CNT_WC  (OFF_W2 + CNT_W2)

// ---------------- scratch (static device globals; no allocation) -------------
static __device__ __align__(16) float g_h0  [(size_t)NN * IND];
static __device__ __align__(16) float g_h1  [(size_t)NN * HID1];
static __device__ __align__(16) float g_o1  [(size_t)NN * HID1];
static __device__ __align__(16) float g_h2  [(size_t)NN * C2];
static __device__ __align__(16) float g_wt  [CNT_WC];   // transposed + tf32-rounded weights

static __device__ __align__(16) float g_as1[NN * H1];
static __device__ __align__(16) float g_ad1[NN * H1];
static __device__ float g_as2[NN];
static __device__ float g_ad2[NN];

static __device__ __align__(16) float g_w1[(size_t)ET_MAX * H1];
static __device__ float g_w2[ET_MAX];

static __device__ int g_src[ET_MAX];
static __device__ int g_dst[ET_MAX];
static __device__ int g_deg[NN];
static __device__ int g_cursor[NN];
static __device__ int g_rowstart[NN + 1];
static __device__ int g_csr_src[ET_MAX];
static __device__ int g_is64;

// ---------------- mma helpers -------------------------------------------------
__device__ __forceinline__ uint32_t f2tf32(float f) {
    uint32_t u;
    asm("cvt.rna.tf32.f32 %0, %1;" : "=r"(u) : "f"(f));
    return u;
}

__device__ __forceinline__ void mma_tf32(float* c, const uint32_t* a, const uint32_t* b) {
    asm volatile(
        "mma.sync.aligned.m16n8k8.row.col.f32.tf32.tf32.f32 "
        "{%0,%1,%2,%3},{%4,%5,%6,%7},{%8,%9},{%0,%1,%2,%3};"
        : "+f"(c[0]), "+f"(c[1]), "+f"(c[2]), "+f"(c[3])
        : "r"(a[0]), "r"(a[1]), "r"(a[2]), "r"(a[3]), "r"(b[0]), "r"(b[1]));
}

__device__ __forceinline__ void ldsm_x4(uint32_t* d, uint32_t addr) {
    asm volatile("ldmatrix.sync.aligned.m8n8.x4.shared.b16 {%0,%1,%2,%3}, [%4];"
        : "=r"(d[0]), "=r"(d[1]), "=r"(d[2]), "=r"(d[3]) : "r"(addr));
}

// ---------------- small kernels -----------------------------------------------

__global__ void k_detect(const void* ei) {
    const unsigned int* u = (const unsigned int*)ei;
    int is64 = 1;
    #pragma unroll
    for (int i = 1; i < 16; i += 2)
        if (u[i] != 0u) is64 = 0;
    g_is64 = is64;
}

__global__ void k_init(int n) {
    int i = blockIdx.x * blockDim.x + threadIdx.x;
    if (i < n) { g_deg[i] = 0; g_cursor[i] = 0; }
}

// Build int32 src/dst lists with self-loops appended; fused degree histogram.
__global__ void k_prep(const void* ei, int E, int n) {
    int i = blockIdx.x * blockDim.x + threadIdx.x;
    int tot = E + n;
    if (i >= tot) return;
    int s, d;
    if (i < E) {
        if (g_is64) {
            const long long* p = (const long long*)ei;
            s = (int)p[i]; d = (int)p[E + i];
        } else {
            const int* p = (const int*)ei;
            s = p[i]; d = p[E + i];
        }
    } else {
        s = d = i - E;
    }
    g_src[i] = s; g_dst[i] = d;
    atomicAdd(&g_deg[d], 1);
}

// Weight transpose + tf32 round: in [K][N] row-major -> out [N][K] row-major
__global__ void k_transpose(const float* __restrict__ in, float* __restrict__ out,
                            int K, int N) {
    __shared__ float tile[32][33];
    int kb = blockIdx.x * 32, nb = blockIdx.y * 32;
    int tx = threadIdx.x, ty = threadIdx.y;   // 32 x 8
    #pragma unroll
    for (int i = 0; i < 32; i += 8)
        tile[ty + i][tx] = in[(size_t)(kb + ty + i) * N + nb + tx];
    __syncthreads();
    #pragma unroll
    for (int i = 0; i < 32; i += 8)
        out[(size_t)(nb + ty + i) * K + kb + tx] =
            __uint_as_float(f2tf32(tile[tx][ty + i]));
}

__global__ void __launch_bounds__(1024) k_scan(int n) {
    __shared__ int s_sum[1024];
    int t = threadIdx.x;
    const int CH = (NN + 1023) / 1024;   // 49
    int base = t * CH;
    int sum = 0;
    for (int i = 0; i < CH; i++) {
        int idx = base + i;
        if (idx < n) sum += g_deg[idx];
    }
    s_sum[t] = sum;
    __syncthreads();
    for (int o = 1; o < 1024; o <<= 1) {
        int v = 0;
        if (t >= o) v = s_sum[t - o];
        __syncthreads();
        if (t >= o) s_sum[t] += v;
        __syncthreads();
    }
    int run = (t > 0) ? s_sum[t - 1] : 0;
    for (int i = 0; i < CH; i++) {
        int idx = base + i;
        if (idx < n) { g_rowstart[idx] = run; run += g_deg[idx]; }
    }
    if (t == 1023) g_rowstart[n] = s_sum[1023];
}

__global__ void k_scatter(int tot) {
    int i = blockIdx.x * blockDim.x + threadIdx.x;
    if (i >= tot) return;
    int d = g_dst[i];
    int pos = atomicAdd(&g_cursor[d], 1);
    g_csr_src[g_rowstart[d] + pos] = g_src[i];
}

// ---------------- TF32 tensor-core GEMM with ldmatrix fragments ----------------
// C[M,N] = A[M,K] @ B[K,N];  BT = B transposed [N][K], tf32-pre-rounded.
// Block 128x128x32, 256 threads = 8 warps (4x2), warp tile 32x64,
// register-prefetch single-buffer pipeline, LDSM.x4 fragment loads.
__global__ void __launch_bounds__(256, 1) k_mma_gemm(
    const float* __restrict__ A, const float* __restrict__ BT,
    float* __restrict__ C, int M, int N, int K)
{
    __shared__ uint32_t As[128][36];
    __shared__ uint32_t Bs[128][36];

    int tid = threadIdx.x;
    int lane = tid & 31;
    int wid = tid >> 5;
    int t = lane & 3;
    int warp_m = wid & 3;     // 0..3 (32 rows each)
    int warp_n = wid >> 2;    // 0..1 (64 cols each)
    int row0 = blockIdx.y * 128;
    int col0 = blockIdx.x * 128;

    uint32_t as_base = (uint32_t)__cvta_generic_to_shared(&As[0][0]);
    uint32_t bs_base = (uint32_t)__cvta_generic_to_shared(&Bs[0][0]);

    // LDSM per-lane address components
    int a_row_off = warp_m * 32 + (lane & 15);
    int a_col_off = 4 * (lane >> 4);
    int b_row_off = warp_n * 64 + ((lane >> 4) << 3) + (lane & 7);
    int b_col_off = 4 * ((lane >> 3) & 1);

    float acc[2][8][4];
    #pragma unroll
    for (int mt = 0; mt < 2; mt++)
        #pragma unroll
        for (int nt = 0; nt < 8; nt++)
            #pragma unroll
            for (int i = 0; i < 4; i++) acc[mt][nt][i] = 0.f;

    float4 pa[4], pb[4];
    int nIter = K >> 5;

    // prologue: load k-tile 0
    #pragma unroll
    for (int i = 0; i < 4; i++) {
        int idx = tid + 256 * i;
        int r = idx >> 3, c4 = idx & 7;
        int gr = row0 + r;
        pa[i] = (gr < M) ? *(const float4*)(A + (size_t)gr * K + c4 * 4)
                         : make_float4(0.f, 0.f, 0.f, 0.f);
        pb[i] = *(const float4*)(BT + (size_t)(col0 + r) * K + c4 * 4);
    }
    #pragma unroll
    for (int i = 0; i < 4; i++) {
        int idx = tid + 256 * i;
        int r = idx >> 3, c4 = idx & 7;
        *(uint4*)&As[r][c4 * 4] =
            make_uint4(f2tf32(pa[i].x), f2tf32(pa[i].y), f2tf32(pa[i].z), f2tf32(pa[i].w));
        *(uint4*)&Bs[r][c4 * 4] = *(uint4*)&pb[i];   // BT already tf32 bits
    }
    __syncthreads();

    for (int it = 0; it < nIter; it++) {
        bool more = (it + 1 < nIter);
        if (more) {
            int k0g = (it + 1) * 32;
            #pragma unroll
            for (int i = 0; i < 4; i++) {
                int idx = tid + 256 * i;
                int r = idx >> 3, c4 = idx & 7;
                int gr = row0 + r;
                pa[i] = (gr < M) ? *(const float4*)(A + (size_t)gr * K + k0g + c4 * 4)
                                 : make_float4(0.f, 0.f, 0.f, 0.f);
                pb[i] = *(const float4*)(BT + (size_t)(col0 + r) * K + k0g + c4 * 4);
            }
        }

        // compute on current smem tile — LDSM fragment loads
        #pragma unroll
        for (int kk = 0; kk < 4; kk++) {
            uint32_t af[2][4];
            #pragma unroll
            for (int mt = 0; mt < 2; mt++) {
                int row = a_row_off + mt * 16;
                int col = kk * 8 + a_col_off;
                ldsm_x4(af[mt], as_base + (uint32_t)(row * 36 + col) * 4u);
            }
            uint32_t bq[4][4];
            #pragma unroll
            for (int p = 0; p < 4; p++) {
                int row = b_row_off + p * 16;
                int col = kk * 8 + b_col_off;
                ldsm_x4(bq[p], bs_base + (uint32_t)(row * 36 + col) * 4u);
            }
            #pragma unroll
            for (int nt = 0; nt < 8; nt++) {
                uint32_t bf[2] = { bq[nt >> 1][(nt & 1) * 2], bq[nt >> 1][(nt & 1) * 2 + 1] };
                mma_tf32(acc[0][nt], af[0], bf);
                mma_tf32(acc[1][nt], af[1], bf);
            }
        }

        if (more) {
            __syncthreads();
            #pragma unroll
            for (int i = 0; i < 4; i++) {
                int idx = tid + 256 * i;
                int r = idx >> 3, c4 = idx & 7;
                *(uint4*)&As[r][c4 * 4] =
                    make_uint4(f2tf32(pa[i].x), f2tf32(pa[i].y), f2tf32(pa[i].z), f2tf32(pa[i].w));
                *(uint4*)&Bs[r][c4 * 4] = *(uint4*)&pb[i];
            }
            __syncthreads();
        }
    }

    // epilogue
    int g = lane >> 2;
    #pragma unroll
    for (int mt = 0; mt < 2; mt++) {
        int r0 = row0 + warp_m * 32 + mt * 16 + g;
        #pragma unroll
        for (int nt = 0; nt < 8; nt++) {
            int c = col0 + warp_n * 64 + nt * 8 + 2 * t;
            if (r0 < M)
                *(float2*)(C + (size_t)r0 * N + c) = make_float2(acc[mt][nt][0], acc[mt][nt][1]);
            if (r0 + 8 < M)
                *(float2*)(C + (size_t)(r0 + 8) * N + c) = make_float2(acc[mt][nt][2], acc[mt][nt][3]);
        }
    }
}

// Encoder epilogue: h0 += node_attr @ enc_W[384:386] + enc_b   (float4)
__global__ void k_enc_epi(const float* __restrict__ na,
                          const float* __restrict__ encW,
                          const float* __restrict__ encb, int n) {
    int idx = blockIdx.x * blockDim.x + threadIdx.x;     // float4 index
    int total = n * (IND / 4);
    if (idx >= total) return;
    int node = idx / (IND / 4);
    int j4 = idx - node * (IND / 4);
    float a0 = na[node * 2 + 0];
    float a1 = na[node * 2 + 1];
    float4 v  = *(float4*)(g_h0 + (size_t)idx * 4);
    float4 w0 = *(const float4*)(encW + (size_t)384 * IND + j4 * 4);
    float4 w1 = *(const float4*)(encW + (size_t)385 * IND + j4 * 4);
    float4 bb = *(const float4*)(encb + j4 * 4);
    v.x += a0 * w0.x + a1 * w1.x + bb.x;
    v.y += a0 * w0.y + a1 * w1.y + bb.y;
    v.z += a0 * w0.z + a1 * w1.z + bb.z;
    v.w += a0 * w0.w + a1 * w1.w + bb.w;
    *(float4*)(g_h0 + (size_t)idx * 4) = v;
}

// alpha_s / alpha_d for layer 1: one warp per (node, head)
__global__ void k_alpha1(const float* __restrict__ a_src,
                         const float* __restrict__ a_dst, int n) {
    int w = (blockIdx.x * blockDim.x + threadIdx.x) >> 5;
    int lane = threadIdx.x & 31;
    if (w >= n * H1) return;
    int node = w >> 2, head = w & 3;
    const float* hp = g_h1 + (size_t)node * HID1 + head * C1;
    const float* asp = a_src + head * C1;
    const float* adp = a_dst + head * C1;
    float s = 0.f, d = 0.f;
    #pragma unroll
    for (int c = lane; c < C1; c += 32) {
        float v = hp[c];
        s += v * asp[c];
        d += v * adp[c];
    }
    #pragma unroll
    for (int o = 16; o > 0; o >>= 1) {
        s += __shfl_xor_sync(0xffffffffu, s, o);
        d += __shfl_xor_sync(0xffffffffu, d, o);
    }
    if (lane == 0) { g_as1[node * H1 + head] = s; g_ad1[node * H1 + head] = d; }
}

// alpha_s / alpha_d for layer 2: one warp per node
__global__ void k_alpha2(const float* __restrict__ a_src,
                         const float* __restrict__ a_dst, int n) {
    int w = (blockIdx.x * blockDim.x + threadIdx.x) >> 5;
    int lane = threadIdx.x & 31;
    if (w >= n) return;
    const float* hp = g_h2 + (size_t)w * C2;
    float s = 0.f, d = 0.f;
    #pragma unroll
    for (int c = lane; c < C2; c += 32) {
        float v = hp[c];
        s += v * a_src[c];
        d += v * a_dst[c];
    }
    #pragma unroll
    for (int o = 16; o > 0; o >>= 1) {
        s += __shfl_xor_sync(0xffffffffu, s, o);
        d += __shfl_xor_sync(0xffffffffu, d, o);
    }
    if (lane == 0) { g_as2[w] = s; g_ad2[w] = d; }
}

__device__ __forceinline__ float leaky(float e) {
    return (e >= 0.f) ? e : NEG_SLOPE * e;
}

// Fused layer-1 attention softmax + aggregation + bias + ELU.
// One 256-thread block per destination node.
__global__ void __launch_bounds__(256) k_attn_agg1(const float* __restrict__ b1) {
    int d = blockIdx.x;
    int t = threadIdx.x;
    int lane = t & 31;
    int beg = g_rowstart[d];
    int end = g_rowstart[d + 1];
    int deg = end - beg;

    __shared__ float s_inv[4];

    if (t < 32) {  // warp 0: softmax stats
        float4 ad = *(const float4*)(g_ad1 + d * 4);
        float m0 = -INFINITY, m1 = -INFINITY, m2 = -INFINITY, m3 = -INFINITY;
        for (int j = lane; j < deg; j += 32) {
            int s = g_csr_src[beg + j];
            float4 as = *(const float4*)(g_as1 + s * 4);
            float e0 = leaky(as.x + ad.x);
            float e1 = leaky(as.y + ad.y);
            float e2 = leaky(as.z + ad.z);
            float e3 = leaky(as.w + ad.w);
            *(float4*)(g_w1 + (size_t)(beg + j) * 4) = make_float4(e0, e1, e2, e3);
            m0 = fmaxf(m0, e0); m1 = fmaxf(m1, e1);
            m2 = fmaxf(m2, e2); m3 = fmaxf(m3, e3);
        }
        #pragma unroll
        for (int o = 16; o > 0; o >>= 1) {
            m0 = fmaxf(m0, __shfl_xor_sync(0xffffffffu, m0, o));
            m1 = fmaxf(m1, __shfl_xor_sync(0xffffffffu, m1, o));
            m2 = fmaxf(m2, __shfl_xor_sync(0xffffffffu, m2, o));
            m3 = fmaxf(m3, __shfl_xor_sync(0xffffffffu, m3, o));
        }
        float s0 = 0.f, s1 = 0.f, s2 = 0.f, s3 = 0.f;
        for (int j = lane; j < deg; j += 32) {
            float4 e = *(const float4*)(g_w1 + (size_t)(beg + j) * 4);
            float w0 = __expf(e.x - m0), w1 = __expf(e.y - m1);
            float w2 = __expf(e.z - m2), w3 = __expf(e.w - m3);
            *(float4*)(g_w1 + (size_t)(beg + j) * 4) = make_float4(w0, w1, w2, w3);
            s0 += w0; s1 += w1; s2 += w2; s3 += w3;
        }
        #pragma unroll
        for (int o = 16; o > 0; o >>= 1) {
            s0 += __shfl_xor_sync(0xffffffffu, s0, o);
            s1 += __shfl_xor_sync(0xffffffffu, s1, o);
            s2 += __shfl_xor_sync(0xffffffffu, s2, o);
            s3 += __shfl_xor_sync(0xffffffffu, s3, o);
        }
        if (lane == 0) {
            s_inv[0] = 1.f / (s0 + 1e-16f);
            s_inv[1] = 1.f / (s1 + 1e-16f);
            s_inv[2] = 1.f / (s2 + 1e-16f);
            s_inv[3] = 1.f / (s3 + 1e-16f);
        }
    }
    __syncthreads();

    float acc0 = 0.f, acc1 = 0.f, acc2 = 0.f, acc3 = 0.f;
    int j = 0;
    for (; j + 4 <= deg; j += 4) {
        int s0 = g_csr_src[beg + j];
        int s1 = g_csr_src[beg + j + 1];
        int s2 = g_csr_src[beg + j + 2];
        int s3 = g_csr_src[beg + j + 3];
        float4 w0 = *(const float4*)(g_w1 + (size_t)(beg + j) * 4);
        float4 w1 = *(const float4*)(g_w1 + (size_t)(beg + j + 1) * 4);
        float4 w2 = *(const float4*)(g_w1 + (size_t)(beg + j + 2) * 4);
        float4 w3 = *(const float4*)(g_w1 + (size_t)(beg + j + 3) * 4);
        const float* p0 = g_h1 + (size_t)s0 * HID1;
        const float* p1 = g_h1 + (size_t)s1 * HID1;
        const float* p2 = g_h1 + (size_t)s2 * HID1;
        const float* p3 = g_h1 + (size_t)s3 * HID1;
        acc0 += p0[t] * w0.x + p1[t] * w1.x + p2[t] * w2.x + p3[t] * w3.x;
        acc1 += p0[256 + t] * w0.y + p1[256 + t] * w1.y + p2[256 + t] * w2.y + p3[256 + t] * w3.y;
        acc2 += p0[512 + t] * w0.z + p1[512 + t] * w1.z + p2[512 + t] * w2.z + p3[512 + t] * w3.z;
        acc3 += p0[768 + t] * w0.w + p1[768 + t] * w1.w + p2[768 + t] * w2.w + p3[768 + t] * w3.w;
    }
    for (; j < deg; j++) {
        int s = g_csr_src[beg + j];
        float4 w = *(const float4*)(g_w1 + (size_t)(beg + j) * 4);
        const float* hs = g_h1 + (size_t)s * HID1;
        acc0 += hs[t] * w.x;
        acc1 += hs[256 + t] * w.y;
        acc2 += hs[512 + t] * w.z;
        acc3 += hs[768 + t] * w.w;
    }
    float v0 = acc0 * s_inv[0] + b1[t];
    float v1 = acc1 * s_inv[1] + b1[256 + t];
    float v2 = acc2 * s_inv[2] + b1[512 + t];
    float v3 = acc3 * s_inv[3] + b1[768 + t];
    float* od = g_o1 + (size_t)d * HID1;
    od[t]       = (v0 > 0.f) ? v0 : expm1f(v0);
    od[256 + t] = (v1 > 0.f) ? v1 : expm1f(v1);
    od[512 + t] = (v2 > 0.f) ? v2 : expm1f(v2);
    od[768 + t] = (v3 > 0.f) ? v3 : expm1f(v3);
}

// Fused layer-2 attention softmax + aggregation + bias -> out.
// One 128-thread block per destination node.
__global__ void __launch_bounds__(128) k_attn_agg2(const float* __restrict__ b2,
                                                   float* __restrict__ out) {
    int d = blockIdx.x;
    int t = threadIdx.x;
    int lane = t & 31;
    int beg = g_rowstart[d];
    int end = g_rowstart[d + 1];
    int deg = end - beg;

    __shared__ float s_inv;

    if (t < 32) {
        float ad = g_ad2[d];
        float m = -INFINITY;
        for (int j = lane; j < deg; j += 32) {
            int s = g_csr_src[beg + j];
            float e = leaky(g_as2[s] + ad);
            g_w2[beg + j] = e;
            m = fmaxf(m, e);
        }
        #pragma unroll
        for (int o = 16; o > 0; o >>= 1)
            m = fmaxf(m, __shfl_xor_sync(0xffffffffu, m, o));
        float sum = 0.f;
        for (int j = lane; j < deg; j += 32) {
            float w = __expf(g_w2[beg + j] - m);
            g_w2[beg + j] = w;
            sum += w;
        }
        #pragma unroll
        for (int o = 16; o > 0; o >>= 1)
            sum += __shfl_xor_sync(0xffffffffu, sum, o);
        if (lane == 0) s_inv = 1.f / (sum + 1e-16f);
    }
    __syncthreads();

    float acc = 0.f;
    int j = 0;
    for (; j + 4 <= deg; j += 4) {
        int s0 = g_csr_src[beg + j];
        int s1 = g_csr_src[beg + j + 1];
        int s2 = g_csr_src[beg + j + 2];
        int s3 = g_csr_src[beg + j + 3];
        float w0 = g_w2[beg + j], w1 = g_w2[beg + j + 1];
        float w2 = g_w2[beg + j + 2], w3 = g_w2[beg + j + 3];
        acc += g_h2[(size_t)s0 * C2 + t] * w0 + g_h2[(size_t)s1 * C2 + t] * w1
             + g_h2[(size_t)s2 * C2 + t] * w2 + g_h2[(size_t)s3 * C2 + t] * w3;
    }
    for (; j < deg; j++) {
        int s = g_csr_src[beg + j];
        acc += g_h2[(size_t)s * C2 + t] * g_w2[beg + j];
    }
    out[(size_t)d * C2 + t] = acc * s_inv + b2[t];
}

// ---------------- host launcher ----------------------------------------------
extern "C" void kernel_launch(void* const* d_in, const int* in_sizes, int n_in,
                              void* d_out, int out_size) {
    const float* x       = (const float*)d_in[0];
    const float* na      = (const float*)d_in[1];
    const void*  ei      = d_in[2];
    const float* encW    = (const float*)d_in[3];
    const float* encb    = (const float*)d_in[4];
    const float* W1      = (const float*)d_in[5];
    const float* a_src1  = (const float*)d_in[6];
    const float* a_dst1  = (const float*)d_in[7];
    const float* b1      = (const float*)d_in[8];
    const float* W2      = (const float*)d_in[9];
    const float* a_src2  = (const float*)d_in[10];
    const float* a_dst2  = (const float*)d_in[11];
    const float* b2      = (const float*)d_in[12];
    float* out = (float*)d_out;

    int n = in_sizes[0] / IND;
    int E = in_sizes[2] / 2;
    int tot = E + n;

    float *p_h0, *p_h1, *p_o1, *p_h2, *p_wt;
    cudaGetSymbolAddress((void**)&p_h0, g_h0);
    cudaGetSymbolAddress((void**)&p_h1, g_h1);
    cudaGetSymbolAddress((void**)&p_o1, g_o1);
    cudaGetSymbolAddress((void**)&p_h2, g_h2);
    cudaGetSymbolAddress((void**)&p_wt, g_wt);

    // ---- weight transposes (tf32-rounded) ----
    {
        dim3 blk(32, 8);
        k_transpose<<<dim3(IND / 32, IND / 32), blk>>>(encW, p_wt + OFF_ENC, IND, IND);
        k_transpose<<<dim3(IND / 32, HID1 / 32), blk>>>(W1, p_wt + OFF_W1, IND, HID1);
        k_transpose<<<dim3(HID1 / 32, C2 / 32), blk>>>(W2, p_wt + OFF_W2, HID1, C2);
    }

    // ---- CSR build ----
    k_detect<<<1, 1>>>(ei);
    k_init<<<(n + 255) / 256, 256>>>(n);
    k_prep<<<(tot + 255) / 256, 256>>>(ei, E, n);

    // ---- encoder ----
    {
        dim3 grid(IND / 128, (n + 127) / 128);
        k_mma_gemm<<<grid, 256>>>(x, p_wt + OFF_ENC, p_h0, n, IND, IND);
        k_enc_epi<<<(n * (IND / 4) + 255) / 256, 256>>>(na, encW, encb, n);
    }

    // CSR back half
    k_scan<<<1, 1024>>>(n);
    k_scatter<<<(tot + 255) / 256, 256>>>(tot);

    // ---- GAT layer 1 ----
    {
        dim3 grid(HID1 / 128, (n + 127) / 128);
        k_mma_gemm<<<grid, 256>>>(p_h0, p_wt + OFF_W1, p_h1, n, HID1, IND);
    }
    k_alpha1<<<((n * H1 * 32) + 127) / 128, 128>>>(a_src1, a_dst1, n);
    k_attn_agg1<<<n, 256>>>(b1);

    // ---- GAT layer 2 ----
    {
        dim3 grid(C2 / 128, (n + 127) / 128);
        k_mma_gemm<<<grid, 256>>>(p_o1, p_wt + OFF_W2, p_h2, n, C2, HID1);
    }
    k_alpha2<<<((n * 32) + 127) / 128, 128>>>(a_src2, a_dst2, n);
    k_attn_agg2<<<n, 128>>>(b2, out);
}

// round 11
// speedup vs baseline: 1.2044x; 1.1118x over previous
#include <cuda_runtime.h>
#include <math.h>
#include <stdint.h>

// Problem constants (fixed by the dataset)
#define NN      50000
#define EE_MAX  500000
#define ET_MAX  (NN + EE_MAX)
#define IND     384
#define HID1    1024   // 4 heads * 256
#define C1      256
#define H1      4
#define C2      128
#define NEG_SLOPE 0.2f

// transposed-weight buffer offsets (floats)
#define OFF_ENC 0
#define CNT_ENC (384 * 384)
#define OFF_W1  (CNT_ENC)
#define CNT_W1  (384 * 1024)
#define OFF_W2  (OFF_W1 + CNT_W1)
#define CNT_W2  (1024 * 128)
#define CNT_WC  (OFF_W2 + CNT_W2)

// ---------------- scratch (static device globals; no allocation) -------------
static __device__ __align__(16) float g_h0  [(size_t)NN * IND];
static __device__ __align__(16) float g_h1  [(size_t)NN * HID1];
static __device__ __align__(16) float g_o1  [(size_t)NN * HID1];
static __device__ __align__(16) float g_h2  [(size_t)NN * C2];
static __device__ __align__(16) float g_wt  [CNT_WC];   // transposed + tf32-rounded weights

static __device__ __align__(16) float g_as1[NN * H1];
static __device__ __align__(16) float g_ad1[NN * H1];
static __device__ float g_as2[NN];
static __device__ float g_ad2[NN];

static __device__ __align__(16) float g_w1[(size_t)ET_MAX * H1];
static __device__ float g_w2[ET_MAX];

static __device__ int g_src[ET_MAX];
static __device__ int g_dst[ET_MAX];
static __device__ int g_deg[NN];
static __device__ int g_cursor[NN];
static __device__ int g_rowstart[NN + 1];
static __device__ int g_csr_src[ET_MAX];
static __device__ int g_is64;

// ---------------- mma helpers -------------------------------------------------
__device__ __forceinline__ uint32_t f2tf32(float f) {
    uint32_t u;
    asm("cvt.rna.tf32.f32 %0, %1;" : "=r"(u) : "f"(f));
    return u;
}

__device__ __forceinline__ void mma_tf32(float* c, const uint32_t* a, const uint32_t* b) {
    asm volatile(
        "mma.sync.aligned.m16n8k8.row.col.f32.tf32.tf32.f32 "
        "{%0,%1,%2,%3},{%4,%5,%6,%7},{%8,%9},{%0,%1,%2,%3};"
        : "+f"(c[0]), "+f"(c[1]), "+f"(c[2]), "+f"(c[3])
        : "r"(a[0]), "r"(a[1]), "r"(a[2]), "r"(a[3]), "r"(b[0]), "r"(b[1]));
}

__device__ __forceinline__ void ldsm_x4(uint32_t* d, uint32_t addr) {
    asm volatile("ldmatrix.sync.aligned.m8n8.x4.shared.b16 {%0,%1,%2,%3}, [%4];"
        : "=r"(d[0]), "=r"(d[1]), "=r"(d[2]), "=r"(d[3]) : "r"(addr));
}

// ---------------- small kernels -----------------------------------------------

// zero deg/cursor; thread 0 of block 0 also does int64/int32 detection
__global__ void k_init(const void* ei, int n) {
    int i = blockIdx.x * blockDim.x + threadIdx.x;
    if (i == 0) {
        const unsigned int* u = (const unsigned int*)ei;
        int is64 = 1;
        #pragma unroll
        for (int k = 1; k < 16; k += 2)
            if (u[k] != 0u) is64 = 0;
        g_is64 = is64;
    }
    if (i < n) { g_deg[i] = 0; g_cursor[i] = 0; }
}

// Build int32 src/dst lists with self-loops appended; fused degree histogram.
__global__ void k_prep(const void* ei, int E, int n) {
    int i = blockIdx.x * blockDim.x + threadIdx.x;
    int tot = E + n;
    if (i >= tot) return;
    int s, d;
    if (i < E) {
        if (g_is64) {
            const long long* p = (const long long*)ei;
            s = (int)p[i]; d = (int)p[E + i];
        } else {
            const int* p = (const int*)ei;
            s = p[i]; d = p[E + i];
        }
    } else {
        s = d = i - E;
    }
    g_src[i] = s; g_dst[i] = d;
    atomicAdd(&g_deg[d], 1);
}

// Weight transpose + tf32 round: in [K][N] row-major -> out [N][K] row-major
__global__ void k_transpose(const float* __restrict__ in, float* __restrict__ out,
                            int K, int N) {
    __shared__ float tile[32][33];
    int kb = blockIdx.x * 32, nb = blockIdx.y * 32;
    int tx = threadIdx.x, ty = threadIdx.y;   // 32 x 8
    #pragma unroll
    for (int i = 0; i < 32; i += 8)
        tile[ty + i][tx] = in[(size_t)(kb + ty + i) * N + nb + tx];
    __syncthreads();
    #pragma unroll
    for (int i = 0; i < 32; i += 8)
        out[(size_t)(nb + ty + i) * K + kb + tx] =
            __uint_as_float(f2tf32(tile[tx][ty + i]));
}

__global__ void __launch_bounds__(1024) k_scan(int n) {
    __shared__ int s_sum[1024];
    int t = threadIdx.x;
    const int CH = (NN + 1023) / 1024;   // 49
    int base = t * CH;
    int sum = 0;
    for (int i = 0; i < CH; i++) {
        int idx = base + i;
        if (idx < n) sum += g_deg[idx];
    }
    s_sum[t] = sum;
    __syncthreads();
    for (int o = 1; o < 1024; o <<= 1) {
        int v = 0;
        if (t >= o) v = s_sum[t - o];
        __syncthreads();
        if (t >= o) s_sum[t] += v;
        __syncthreads();
    }
    int run = (t > 0) ? s_sum[t - 1] : 0;
    for (int i = 0; i < CH; i++) {
        int idx = base + i;
        if (idx < n) { g_rowstart[idx] = run; run += g_deg[idx]; }
    }
    if (t == 1023) g_rowstart[n] = s_sum[1023];
}

__global__ void k_scatter(int tot) {
    int i = blockIdx.x * blockDim.x + threadIdx.x;
    if (i >= tot) return;
    int d = g_dst[i];
    int pos = atomicAdd(&g_cursor[d], 1);
    g_csr_src[g_rowstart[d] + pos] = g_src[i];
}

// ---------------- TF32 tensor-core GEMM with ldmatrix fragments ----------------
// C[M,N] = A[M,K] @ B[K,N];  BT = B transposed [N][K], tf32-pre-rounded.
// Block 128x128x32, 256 threads = 8 warps (4x2), warp tile 32x64,
// register-prefetch single-buffer pipeline, LDSM.x4 fragment loads.
__global__ void __launch_bounds__(256, 1) k_mma_gemm(
    const float* __restrict__ A, const float* __restrict__ BT,
    float* __restrict__ C, int M, int N, int K)
{
    __shared__ uint32_t As[128][36];
    __shared__ uint32_t Bs[128][36];

    int tid = threadIdx.x;
    int lane = tid & 31;
    int wid = tid >> 5;
    int t = lane & 3;
    int warp_m = wid & 3;
    int warp_n = wid >> 2;
    int row0 = blockIdx.y * 128;
    int col0 = blockIdx.x * 128;

    uint32_t as_base = (uint32_t)__cvta_generic_to_shared(&As[0][0]);
    uint32_t bs_base = (uint32_t)__cvta_generic_to_shared(&Bs[0][0]);

    int a_row_off = warp_m * 32 + (lane & 15);
    int a_col_off = 4 * (lane >> 4);
    int b_row_off = warp_n * 64 + ((lane >> 4) << 3) + (lane & 7);
    int b_col_off = 4 * ((lane >> 3) & 1);

    float acc[2][8][4];
    #pragma unroll
    for (int mt = 0; mt < 2; mt++)
        #pragma unroll
        for (int nt = 0; nt < 8; nt++)
            #pragma unroll
            for (int i = 0; i < 4; i++) acc[mt][nt][i] = 0.f;

    float4 pa[4], pb[4];
    int nIter = K >> 5;

    #pragma unroll
    for (int i = 0; i < 4; i++) {
        int idx = tid + 256 * i;
        int r = idx >> 3, c4 = idx & 7;
        int gr = row0 + r;
        pa[i] = (gr < M) ? *(const float4*)(A + (size_t)gr * K + c4 * 4)
                         : make_float4(0.f, 0.f, 0.f, 0.f);
        pb[i] = *(const float4*)(BT + (size_t)(col0 + r) * K + c4 * 4);
    }
    #pragma unroll
    for (int i = 0; i < 4; i++) {
        int idx = tid + 256 * i;
        int r = idx >> 3, c4 = idx & 7;
        *(uint4*)&As[r][c4 * 4] =
            make_uint4(f2tf32(pa[i].x), f2tf32(pa[i].y), f2tf32(pa[i].z), f2tf32(pa[i].w));
        *(uint4*)&Bs[r][c4 * 4] = *(uint4*)&pb[i];
    }
    __syncthreads();

    for (int it = 0; it < nIter; it++) {
        bool more = (it + 1 < nIter);
        if (more) {
            int k0g = (it + 1) * 32;
            #pragma unroll
            for (int i = 0; i < 4; i++) {
                int idx = tid + 256 * i;
                int r = idx >> 3, c4 = idx & 7;
                int gr = row0 + r;
                pa[i] = (gr < M) ? *(const float4*)(A + (size_t)gr * K + k0g + c4 * 4)
                                 : make_float4(0.f, 0.f, 0.f, 0.f);
                pb[i] = *(const float4*)(BT + (size_t)(col0 + r) * K + k0g + c4 * 4);
            }
        }

        #pragma unroll
        for (int kk = 0; kk < 4; kk++) {
            uint32_t af[2][4];
            #pragma unroll
            for (int mt = 0; mt < 2; mt++) {
                int row = a_row_off + mt * 16;
                int col = kk * 8 + a_col_off;
                ldsm_x4(af[mt], as_base + (uint32_t)(row * 36 + col) * 4u);
            }
            uint32_t bq[4][4];
            #pragma unroll
            for (int p = 0; p < 4; p++) {
                int row = b_row_off + p * 16;
                int col = kk * 8 + b_col_off;
                ldsm_x4(bq[p], bs_base + (uint32_t)(row * 36 + col) * 4u);
            }
            #pragma unroll
            for (int nt = 0; nt < 8; nt++) {
                uint32_t bf[2] = { bq[nt >> 1][(nt & 1) * 2], bq[nt >> 1][(nt & 1) * 2 + 1] };
                mma_tf32(acc[0][nt], af[0], bf);
                mma_tf32(acc[1][nt], af[1], bf);
            }
        }

        if (more) {
            __syncthreads();
            #pragma unroll
            for (int i = 0; i < 4; i++) {
                int idx = tid + 256 * i;
                int r = idx >> 3, c4 = idx & 7;
                *(uint4*)&As[r][c4 * 4] =
                    make_uint4(f2tf32(pa[i].x), f2tf32(pa[i].y), f2tf32(pa[i].z), f2tf32(pa[i].w));
                *(uint4*)&Bs[r][c4 * 4] = *(uint4*)&pb[i];
            }
            __syncthreads();
        }
    }

    int g = lane >> 2;
    #pragma unroll
    for (int mt = 0; mt < 2; mt++) {
        int r0 = row0 + warp_m * 32 + mt * 16 + g;
        #pragma unroll
        for (int nt = 0; nt < 8; nt++) {
            int c = col0 + warp_n * 64 + nt * 8 + 2 * t;
            if (r0 < M)
                *(float2*)(C + (size_t)r0 * N + c) = make_float2(acc[mt][nt][0], acc[mt][nt][1]);
            if (r0 + 8 < M)
                *(float2*)(C + (size_t)(r0 + 8) * N + c) = make_float2(acc[mt][nt][2], acc[mt][nt][3]);
        }
    }
}

// Encoder epilogue: h0 += node_attr @ enc_W[384:386] + enc_b   (float4)
__global__ void k_enc_epi(const float* __restrict__ na,
                          const float* __restrict__ encW,
                          const float* __restrict__ encb, int n) {
    int idx = blockIdx.x * blockDim.x + threadIdx.x;
    int total = n * (IND / 4);
    if (idx >= total) return;
    int node = idx / (IND / 4);
    int j4 = idx - node * (IND / 4);
    float a0 = na[node * 2 + 0];
    float a1 = na[node * 2 + 1];
    float4 v  = *(float4*)(g_h0 + (size_t)idx * 4);
    float4 w0 = *(const float4*)(encW + (size_t)384 * IND + j4 * 4);
    float4 w1 = *(const float4*)(encW + (size_t)385 * IND + j4 * 4);
    float4 bb = *(const float4*)(encb + j4 * 4);
    v.x += a0 * w0.x + a1 * w1.x + bb.x;
    v.y += a0 * w0.y + a1 * w1.y + bb.y;
    v.z += a0 * w0.z + a1 * w1.z + bb.z;
    v.w += a0 * w0.w + a1 * w1.w + bb.w;
    *(float4*)(g_h0 + (size_t)idx * 4) = v;
}

// alpha_s / alpha_d for layer 1: one warp per (node, head)
__global__ void k_alpha1(const float* __restrict__ a_src,
                         const float* __restrict__ a_dst, int n) {
    int w = (blockIdx.x * blockDim.x + threadIdx.x) >> 5;
    int lane = threadIdx.x & 31;
    if (w >= n * H1) return;
    int node = w >> 2, head = w & 3;
    const float* hp = g_h1 + (size_t)node * HID1 + head * C1;
    const float* asp = a_src + head * C1;
    const float* adp = a_dst + head * C1;
    float s = 0.f, d = 0.f;
    #pragma unroll
    for (int c = lane; c < C1; c += 32) {
        float v = hp[c];
        s += v * asp[c];
        d += v * adp[c];
    }
    #pragma unroll
    for (int o = 16; o > 0; o >>= 1) {
        s += __shfl_xor_sync(0xffffffffu, s, o);
        d += __shfl_xor_sync(0xffffffffu, d, o);
    }
    if (lane == 0) { g_as1[node * H1 + head] = s; g_ad1[node * H1 + head] = d; }
}

// alpha_s / alpha_d for layer 2: one warp per node
__global__ void k_alpha2(const float* __restrict__ a_src,
                         const float* __restrict__ a_dst, int n) {
    int w = (blockIdx.x * blockDim.x + threadIdx.x) >> 5;
    int lane = threadIdx.x & 31;
    if (w >= n) return;
    const float* hp = g_h2 + (size_t)w * C2;
    float s = 0.f, d = 0.f;
    #pragma unroll
    for (int c = lane; c < C2; c += 32) {
        float v = hp[c];
        s += v * a_src[c];
        d += v * a_dst[c];
    }
    #pragma unroll
    for (int o = 16; o > 0; o >>= 1) {
        s += __shfl_xor_sync(0xffffffffu, s, o);
        d += __shfl_xor_sync(0xffffffffu, d, o);
    }
    if (lane == 0) { g_as2[w] = s; g_ad2[w] = d; }
}

__device__ __forceinline__ float leaky(float e) {
    return (e >= 0.f) ? e : NEG_SLOPE * e;
}

// Layer-1 softmax: one warp per dst node; writes NORMALIZED alphas to g_w1.
__global__ void __launch_bounds__(256) k_softmax1() {
    int w = (blockIdx.x * blockDim.x + threadIdx.x) >> 5;
    int lane = threadIdx.x & 31;
    if (w >= NN) return;
    int d = w;
    int beg = g_rowstart[d];
    int deg = g_rowstart[d + 1] - beg;

    float4 ad = *(const float4*)(g_ad1 + d * 4);
    float m0 = -INFINITY, m1 = -INFINITY, m2 = -INFINITY, m3 = -INFINITY;
    for (int j = lane; j < deg; j += 32) {
        int s = g_csr_src[beg + j];
        float4 as = *(const float4*)(g_as1 + s * 4);
        float e0 = leaky(as.x + ad.x);
        float e1 = leaky(as.y + ad.y);
        float e2 = leaky(as.z + ad.z);
        float e3 = leaky(as.w + ad.w);
        *(float4*)(g_w1 + (size_t)(beg + j) * 4) = make_float4(e0, e1, e2, e3);
        m0 = fmaxf(m0, e0); m1 = fmaxf(m1, e1);
        m2 = fmaxf(m2, e2); m3 = fmaxf(m3, e3);
    }
    #pragma unroll
    for (int o = 16; o > 0; o >>= 1) {
        m0 = fmaxf(m0, __shfl_xor_sync(0xffffffffu, m0, o));
        m1 = fmaxf(m1, __shfl_xor_sync(0xffffffffu, m1, o));
        m2 = fmaxf(m2, __shfl_xor_sync(0xffffffffu, m2, o));
        m3 = fmaxf(m3, __shfl_xor_sync(0xffffffffu, m3, o));
    }
    float s0 = 0.f, s1 = 0.f, s2 = 0.f, s3 = 0.f;
    for (int j = lane; j < deg; j += 32) {
        float4 e = *(const float4*)(g_w1 + (size_t)(beg + j) * 4);
        float w0 = __expf(e.x - m0), w1 = __expf(e.y - m1);
        float w2 = __expf(e.z - m2), w3 = __expf(e.w - m3);
        *(float4*)(g_w1 + (size_t)(beg + j) * 4) = make_float4(w0, w1, w2, w3);
        s0 += w0; s1 += w1; s2 += w2; s3 += w3;
    }
    #pragma unroll
    for (int o = 16; o > 0; o >>= 1) {
        s0 += __shfl_xor_sync(0xffffffffu, s0, o);
        s1 += __shfl_xor_sync(0xffffffffu, s1, o);
        s2 += __shfl_xor_sync(0xffffffffu, s2, o);
        s3 += __shfl_xor_sync(0xffffffffu, s3, o);
    }
    float i0 = 1.f / (s0 + 1e-16f), i1 = 1.f / (s1 + 1e-16f);
    float i2 = 1.f / (s2 + 1e-16f), i3 = 1.f / (s3 + 1e-16f);
    for (int j = lane; j < deg; j += 32) {
        float4 ww = *(const float4*)(g_w1 + (size_t)(beg + j) * 4);
        ww.x *= i0; ww.y *= i1; ww.z *= i2; ww.w *= i3;
        *(float4*)(g_w1 + (size_t)(beg + j) * 4) = ww;
    }
}

// Layer-1 aggregation for ONE head: channel-sliced so h1[:, head*256:+256]
// (50 MB) stays L2-resident across the whole pass. Block = 128 thr, 2 ch each.
__global__ void __launch_bounds__(128) k_agg1h(int head, const float* __restrict__ b1) {
    int d = blockIdx.x;
    int t = threadIdx.x;
    int beg = g_rowstart[d];
    int deg = g_rowstart[d + 1] - beg;

    const float* hb = g_h1 + head * C1;
    float acc0 = 0.f, acc1 = 0.f;
    int j = 0;
    for (; j + 4 <= deg; j += 4) {
        int s0 = g_csr_src[beg + j];
        int s1 = g_csr_src[beg + j + 1];
        int s2 = g_csr_src[beg + j + 2];
        int s3 = g_csr_src[beg + j + 3];
        float a0 = g_w1[(size_t)(beg + j) * 4 + head];
        float a1 = g_w1[(size_t)(beg + j + 1) * 4 + head];
        float a2 = g_w1[(size_t)(beg + j + 2) * 4 + head];
        float a3 = g_w1[(size_t)(beg + j + 3) * 4 + head];
        const float* p0 = hb + (size_t)s0 * HID1;
        const float* p1 = hb + (size_t)s1 * HID1;
        const float* p2 = hb + (size_t)s2 * HID1;
        const float* p3 = hb + (size_t)s3 * HID1;
        acc0 += p0[t] * a0 + p1[t] * a1 + p2[t] * a2 + p3[t] * a3;
        acc1 += p0[128 + t] * a0 + p1[128 + t] * a1 + p2[128 + t] * a2 + p3[128 + t] * a3;
    }
    for (; j < deg; j++) {
        int s = g_csr_src[beg + j];
        float a = g_w1[(size_t)(beg + j) * 4 + head];
        const float* p = hb + (size_t)s * HID1;
        acc0 += p[t] * a;
        acc1 += p[128 + t] * a;
    }
    float v0 = acc0 + b1[head * C1 + t];
    float v1 = acc1 + b1[head * C1 + 128 + t];
    float* od = g_o1 + (size_t)d * HID1 + head * C1;
    od[t]       = (v0 > 0.f) ? v0 : expm1f(v0);
    od[128 + t] = (v1 > 0.f) ? v1 : expm1f(v1);
}

// Fused layer-2 attention softmax + aggregation + bias -> out.
// One 128-thread block per destination node. (h2 = 25 MB, already L2-resident.)
__global__ void __launch_bounds__(128) k_attn_agg2(const float* __restrict__ b2,
                                                   float* __restrict__ out) {
    int d = blockIdx.x;
    int t = threadIdx.x;
    int lane = t & 31;
    int beg = g_rowstart[d];
    int end = g_rowstart[d + 1];
    int deg = end - beg;

    __shared__ float s_inv;

    if (t < 32) {
        float ad = g_ad2[d];
        float m = -INFINITY;
        for (int j = lane; j < deg; j += 32) {
            int s = g_csr_src[beg + j];
            float e = leaky(g_as2[s] + ad);
            g_w2[beg + j] = e;
            m = fmaxf(m, e);
        }
        #pragma unroll
        for (int o = 16; o > 0; o >>= 1)
            m = fmaxf(m, __shfl_xor_sync(0xffffffffu, m, o));
        float sum = 0.f;
        for (int j = lane; j < deg; j += 32) {
            float w = __expf(g_w2[beg + j] - m);
            g_w2[beg + j] = w;
            sum += w;
        }
        #pragma unroll
        for (int o = 16; o > 0; o >>= 1)
            sum += __shfl_xor_sync(0xffffffffu, sum, o);
        if (lane == 0) s_inv = 1.f / (sum + 1e-16f);
    }
    __syncthreads();

    float acc = 0.f;
    int j = 0;
    for (; j + 4 <= deg; j += 4) {
        int s0 = g_csr_src[beg + j];
        int s1 = g_csr_src[beg + j + 1];
        int s2 = g_csr_src[beg + j + 2];
        int s3 = g_csr_src[beg + j + 3];
        float w0 = g_w2[beg + j], w1 = g_w2[beg + j + 1];
        float w2 = g_w2[beg + j + 2], w3 = g_w2[beg + j + 3];
        acc += g_h2[(size_t)s0 * C2 + t] * w0 + g_h2[(size_t)s1 * C2 + t] * w1
             + g_h2[(size_t)s2 * C2 + t] * w2 + g_h2[(size_t)s3 * C2 + t] * w3;
    }
    for (; j < deg; j++) {
        int s = g_csr_src[beg + j];
        acc += g_h2[(size_t)s * C2 + t] * g_w2[beg + j];
    }
    out[(size_t)d * C2 + t] = acc * s_inv + b2[t];
}

// ---------------- host launcher ----------------------------------------------
extern "C" void kernel_launch(void* const* d_in, const int* in_sizes, int n_in,
                              void* d_out, int out_size) {
    const float* x       = (const float*)d_in[0];
    const float* na      = (const float*)d_in[1];
    const void*  ei      = d_in[2];
    const float* encW    = (const float*)d_in[3];
    const float* encb    = (const float*)d_in[4];
    const float* W1      = (const float*)d_in[5];
    const float* a_src1  = (const float*)d_in[6];
    const float* a_dst1  = (const float*)d_in[7];
    const float* b1      = (const float*)d_in[8];
    const float* W2      = (const float*)d_in[9];
    const float* a_src2  = (const float*)d_in[10];
    const float* a_dst2  = (const float*)d_in[11];
    const float* b2      = (const float*)d_in[12];
    float* out = (float*)d_out;

    int n = in_sizes[0] / IND;
    int E = in_sizes[2] / 2;
    int tot = E + n;

    float *p_h0, *p_h1, *p_o1, *p_h2, *p_wt;
    cudaGetSymbolAddress((void**)&p_h0, g_h0);
    cudaGetSymbolAddress((void**)&p_h1, g_h1);
    cudaGetSymbolAddress((void**)&p_o1, g_o1);
    cudaGetSymbolAddress((void**)&p_h2, g_h2);
    cudaGetSymbolAddress((void**)&p_wt, g_wt);

    dim3 tblk(32, 8);

    // launches 1-3; slot 4 = encoder GEMM (profiled by ncu)
    k_transpose<<<dim3(IND / 32, IND / 32), tblk>>>(encW, p_wt + OFF_ENC, IND, IND);
    k_init<<<(n + 255) / 256, 256>>>(ei, n);
    k_prep<<<(tot + 255) / 256, 256>>>(ei, E, n);
    {
        dim3 grid(IND / 128, (n + 127) / 128);
        k_mma_gemm<<<grid, 256>>>(x, p_wt + OFF_ENC, p_h0, n, IND, IND);
    }
    k_enc_epi<<<(n * (IND / 4) + 255) / 256, 256>>>(na, encW, encb, n);

    // remaining weight transposes + CSR back half
    k_transpose<<<dim3(IND / 32, HID1 / 32), tblk>>>(W1, p_wt + OFF_W1, IND, HID1);
    k_transpose<<<dim3(HID1 / 32, C2 / 32), tblk>>>(W2, p_wt + OFF_W2, HID1, C2);
    k_scan<<<1, 1024>>>(n);
    k_scatter<<<(tot + 255) / 256, 256>>>(tot);

    // ---- GAT layer 1 ----
    {
        dim3 grid(HID1 / 128, (n + 127) / 128);
        k_mma_gemm<<<grid, 256>>>(p_h0, p_wt + OFF_W1, p_h1, n, HID1, IND);
    }
    k_alpha1<<<((n * H1 * 32) + 255) / 256, 256>>>(a_src1, a_dst1, n);
    k_softmax1<<<((n * 32) + 255) / 256, 256>>>();
    for (int h = 0; h < H1; h++)
        k_agg1h<<<n, 128>>>(h, b1);

    // ---- GAT layer 2 ----
    {
        dim3 grid(C2 / 128, (n + 127) / 128);
        k_mma_gemm<<<grid, 256>>>(p_o1, p_wt + OFF_W2, p_h2, n, C2, HID1);
    }
    k_alpha2<<<((n * 32) + 127) / 128, 128>>>(a_src2, a_dst2, n);
    k_attn_agg2<<<n, 128>>>(b2, out);
}